// round 14
// baseline (speedup 1.0000x reference)
#include <cuda_runtime.h>
#include <cuda_fp16.h>
#include <math.h>
#include <stdint.h>

#define G 128
#define G3 (G*G*G)

typedef unsigned long long ull;

// ---------------- packed f32x2 helpers (fp32 L1 kernel) ----------------
#define FMA2(d, a, b, c) \
    asm("fma.rn.f32x2 %0, %1, %2, %3;" : "=l"(d) : "l"(a), "l"(b), "l"(c))
#define PACK2(d, x) \
    asm("mov.b64 %0, {%1, %2};" : "=l"(d) : "r"(__float_as_uint(x)), "r"(__float_as_uint(x)))
#define UNPACK2(lo, hi, v) \
    asm("mov.b64 {%0, %1}, %2;" : "=f"(lo), "=f"(hi) : "l"(v))

__device__ __forceinline__ void cp4(unsigned dst, const void* src, unsigned sz) {
    asm volatile("cp.async.ca.shared.global [%0], [%1], 4, %2;" :: "r"(dst), "l"(src), "r"(sz));
}
__device__ __forceinline__ void cp16(unsigned dst, const void* src) {
    asm volatile("cp.async.cg.shared.global [%0], [%1], 16;" :: "r"(dst), "l"(src));
}
__device__ __forceinline__ void cp_commit() { asm volatile("cp.async.commit_group;"); }
__device__ __forceinline__ void cp_wait0() { asm volatile("cp.async.wait_group 0;"); }

// m16n8k16 fp16 MMA, f32 accumulate
#define MMA16816(d, a, b0v, b1v) \
    asm volatile("mma.sync.aligned.m16n8k16.row.col.f32.f16.f16.f32 " \
        "{%0,%1,%2,%3}, {%4,%5,%6,%7}, {%8,%9}, {%0,%1,%2,%3};" \
        : "+f"((d)[0]), "+f"((d)[1]), "+f"((d)[2]), "+f"((d)[3]) \
        : "r"((a)[0]), "r"((a)[1]), "r"((a)[2]), "r"((a)[3]), \
          "r"(b0v), "r"(b1v))

#define LDSM4(r, addr) \
    asm volatile("ldmatrix.sync.aligned.m8n8.x4.shared.b16 {%0,%1,%2,%3}, [%4];" \
        : "=r"((r)[0]), "=r"((r)[1]), "=r"((r)[2]), "=r"((r)[3]) : "r"(addr))

__device__ __forceinline__ uint32_t packh2(float a, float b) {
    __half2 h = __floats2half2_rn(a, b);
    return *(uint32_t*)&h;
}

// ---------------- scratch buffers ----------------
__device__ float g_bufA[16777216];     // 67MB
__device__ float g_bufB[67108864];     // 268MB
__device__ __half g_bufW[4063232];     // split fp16 weights

// ---------------------------------------------------------------- utilities
__global__ void zero_kernel(float* __restrict__ p, int n) {
    int i = blockIdx.x * blockDim.x + threadIdx.x;
    if (i < n) p[i] = 0.f;
}

// ---------------------------------------------------------------- voxelize
__global__ void voxelize_kernel(const float4* __restrict__ pts, float* __restrict__ grid, int N) {
    int i = blockIdx.x * blockDim.x + threadIdx.x;
    if (i >= N) return;
    float4 p = pts[i];
    if (p.x < -32.f || p.x > 32.f ||
        p.y < -32.f || p.y > 32.f ||
        p.z < -32.f || p.z > 32.f) return;
    int cx = (int)floorf((p.x + 32.f) * 2.f);
    int cy = (int)floorf((p.y + 32.f) * 2.f);
    int cz = (int)floorf((p.z + 32.f) * 2.f);
    cx = cx < 0 ? 0 : (cx > G-1 ? G-1 : cx);
    cy = cy < 0 ? 0 : (cy > G-1 ? G-1 : cy);
    cz = cz < 0 ? 0 : (cz > G-1 ? G-1 : cz);
    int base = (cz * G + cy) * G + cx;
    atomicAdd(&grid[0*G3 + base], p.x);
    atomicAdd(&grid[1*G3 + base], p.y);
    atomicAdd(&grid[2*G3 + base], p.z);
    atomicAdd(&grid[3*G3 + base], p.w);
}

// ---------------------------------------------------------------- fused weight prep (hi/lo fp16)
__global__ void prep_all_kernel(const float* __restrict__ w2, const float* __restrict__ w3,
                                const float* __restrict__ w4, const float* __restrict__ w5,
                                const float* __restrict__ w6, __half* __restrict__ dst) {
    int idx = blockIdx.x * blockDim.x + threadIdx.x;
    const float* w; int CO, CI; size_t off;
    if (idx < 2048)                  { w = w2; CO =  64; CI =  32; off = 0; }
    else if ((idx -= 2048) < 4096)   { w = w3; CO =  64; CI =  64; off = 131072; }
    else if ((idx -= 4096) < 8192)   { w = w4; CO = 128; CI =  64; off = 393216; }
    else if ((idx -= 8192) < 16384)  { w = w5; CO = 128; CI = 128; off = 917504; }
    else if ((idx -= 16384) < 32768) { w = w6; CO = 256; CI = 128; off = 1966080; }
    else return;
    int ci = idx / CO, co = idx - ci * CO;
    const float* ws = w + ((size_t)co * CI + ci) * 27;

    uint32_t h2[16], l2[16];
#pragma unroll
    for (int p = 0; p < 13; p++) {
        float a = ws[2*p], b = ws[2*p+1];
        __half2 h = __floats2half2_rn(a, b);
        float2 hf = __half22float2(h);
        h2[p] = *(uint32_t*)&h;
        l2[p] = packh2(a - hf.x, b - hf.y);
    }
    {
        float a = ws[26];
        __half ha = __float2half_rn(a);
        __half2 h = __halves2half2(ha, __ushort_as_half(0));
        h2[13] = *(uint32_t*)&h;
        l2[13] = packh2(a - __half2float(ha), 0.f);
        h2[14] = h2[15] = l2[14] = l2[15] = 0u;
    }
    uint4* o = (uint4*)(dst + off + (size_t)(ci * CO + co) * 64);
    o[0] = make_uint4(h2[0], h2[1], h2[2], h2[3]);
    o[1] = make_uint4(h2[4], h2[5], h2[6], h2[7]);
    o[2] = make_uint4(h2[8], h2[9], h2[10], h2[11]);
    o[3] = make_uint4(h2[12], h2[13], h2[14], h2[15]);
    o[4] = make_uint4(l2[0], l2[1], l2[2], l2[3]);
    o[5] = make_uint4(l2[4], l2[5], l2[6], l2[7]);
    o[6] = make_uint4(l2[8], l2[9], l2[10], l2[11]);
    o[7] = make_uint4(l2[12], l2[13], l2[14], l2[15]);
}

// ---------------------------------------------------------------- smem size helpers
__host__ __device__ constexpr int align16(int x) { return (x + 15) & ~15; }
__host__ __device__ constexpr int cmax(int a, int b) { return a > b ? a : b; }

template<int STRIDE, int NB, int SOUT>
struct ConvSm {
    static constexpr int TYO  = 128 / SOUT;
    static constexpr int HX   = (SOUT - 1) * STRIDE + 3;
    static constexpr int HY   = (TYO - 1) * STRIDE + 3;
    static constexpr int PX   = (HX + 2) / 2;
    static constexpr int HTOTP = 3 * HY * PX;
    static constexpr int TBLB = align16(HTOTP * 4);
    static constexpr int TILEB = align16(HTOTP * 4);
    static constexpr int A_OFF = TBLB + 2 * TILEB;
    static constexpr int B_OFF = A_OFF + 128 * 80;
    static constexpr int TOTAL = cmax(B_OFF + 2 * NB * 144, 64 * 132 * 4);
};

// ---------------------------------------------------------------- mma implicit-GEMM conv (R11)
template<int CI, int STRIDE, int NB, int SOUT, bool F32OUT>
__global__ void __launch_bounds__(128)
conv_mma_kernel(const __half* __restrict__ in, const __half* __restrict__ Wp,
                const float* __restrict__ gamma, const float* __restrict__ beta,
                void* __restrict__ out, int Sin, int CO)
{
    using SM = ConvSm<STRIDE, NB, SOUT>;
    constexpr int NT = NB / 8;
    constexpr int HY = SM::HY, PX = SM::PX, HTOTP = SM::HTOTP;
    constexpr int TYO = SM::TYO;

    extern __shared__ __align__(16) char sm[];
    int* tbl = (int*)sm;
    char* sA = sm + SM::A_OFF;
    float* sT = (float*)sm;

    const int tid = threadIdx.x;
    const int w = tid >> 5, lane = tid & 31;
    const int g = lane >> 2, tg = lane & 3;

    const uint32_t uTile = (uint32_t)__cvta_generic_to_shared(sm + SM::TBLB);
    const uint32_t uA = (uint32_t)__cvta_generic_to_shared(sA);
    const uint32_t uB = (uint32_t)__cvta_generic_to_shared(sm + SM::B_OFF);
    const uint32_t aBase = uA + (uint32_t)((w * 32 + (lane & 15)) * 80 + (lane >> 4) * 16);
    const uint32_t bBase = uB + (uint32_t)((lane & 7) * 144 + (lane >> 3) * 16);

    const int nby = SOUT / TYO;
    const int bz = blockIdx.x / nby;
    const int by0 = (blockIdx.x % nby) * TYO;
    const int oc0 = blockIdx.y * NB;
    const int vbase = blockIdx.x * 128;

    const int y = tid / SOUT, x = tid % SOUT;
    const int oz = bz * STRIDE - 1, oy = by0 * STRIDE - 1;
    const size_t SinSq = (size_t)Sin * Sin;
    const size_t Sin3 = SinSq * Sin;
    const uint32_t* inu = (const uint32_t*)in;

    for (int idx = tid; idx < HTOTP; idx += 128) {
        int tz = idx / (HY * PX);
        int rem = idx - tz * (HY * PX);
        int ty = rem / PX;
        int px = rem - ty * PX;
        int gz = oz + tz, gy = oy + ty, gx0 = px * 2 - 2;
        int off = -1;
        if ((unsigned)gz < (unsigned)Sin && (unsigned)gy < (unsigned)Sin &&
            gx0 >= 0 && gx0 <= Sin - 2)
            off = (int)(((size_t)gz * SinSq + (size_t)gy * Sin + gx0) >> 1);
        tbl[idx] = off;
    }
    __syncthreads();

    float acc[2][NT][4];
#pragma unroll
    for (int mt = 0; mt < 2; mt++)
#pragma unroll
        for (int nt = 0; nt < NT; nt++)
#pragma unroll
            for (int q = 0; q < 4; q++) acc[mt][nt][q] = 0.f;

    {
        for (int idx = tid; idx < HTOTP; idx += 128) {
            int o = tbl[idx];
            cp4(uTile + idx * 4, inu + (o >= 0 ? o : 0), o >= 0 ? 4u : 0u);
        }
        const char* srcb = (const char*)(Wp + ((size_t)oc0) * 64);
        for (int u = tid; u < NB * 8; u += 128) {
            int co = u >> 3, seg = u & 7;
            cp16(uB + co * 144 + seg * 16, srcb + co * 128 + seg * 16);
        }
        cp_commit();
    }

    for (int ci = 0; ci < CI; ci++) {
        const int s = ci & 1;
        cp_wait0();
        __syncthreads();

        if (ci + 1 < CI) {
            const uint32_t* basep = inu + ((size_t)(ci + 1) * Sin3 >> 1);
            const uint32_t td = uTile + (s ^ 1) * SM::TILEB;
            for (int idx = tid; idx < HTOTP; idx += 128) {
                int o = tbl[idx];
                cp4(td + idx * 4, basep + (o >= 0 ? o : 0), o >= 0 ? 4u : 0u);
            }
            const char* srcb = (const char*)(Wp + ((size_t)(ci + 1) * CO + oc0) * 64);
            const uint32_t bd = uB + (s ^ 1) * (NB * 144);
            for (int u = tid; u < NB * 8; u += 128) {
                int co = u >> 3, seg = u & 7;
                cp16(bd + co * 144 + seg * 16, srcb + co * 128 + seg * 16);
            }
            cp_commit();
        }

        {
            const unsigned short* tp =
                (const unsigned short*)(sm + SM::TBLB + s * SM::TILEB);
            unsigned short t[27];
#pragma unroll
            for (int dz = 0; dz < 3; dz++)
#pragma unroll
                for (int dy = 0; dy < 3; dy++) {
                    const unsigned short* r =
                        tp + (dz * HY + y * STRIDE + dy) * (2 * PX) + x * STRIDE + 1;
                    t[(dz*3+dy)*3 + 0] = r[0];
                    t[(dz*3+dy)*3 + 1] = r[1];
                    t[(dz*3+dy)*3 + 2] = r[2];
                }
            uint32_t h2[16];
#pragma unroll
            for (int j = 0; j < 13; j++)
                h2[j] = (uint32_t)t[2*j] | ((uint32_t)t[2*j+1] << 16);
            h2[13] = (uint32_t)t[26];
            h2[14] = h2[15] = 0u;
            uint4* rowp = (uint4*)(sA + tid * 80);
            rowp[0] = make_uint4(h2[0], h2[1], h2[2], h2[3]);
            rowp[1] = make_uint4(h2[4], h2[5], h2[6], h2[7]);
            rowp[2] = make_uint4(h2[8], h2[9], h2[10], h2[11]);
            rowp[3] = make_uint4(h2[12], h2[13], h2[14], h2[15]);
        }
        __syncwarp();

        const uint32_t bS = bBase + s * (NB * 144);
        uint32_t ah[2][2][4];
#pragma unroll
        for (int mt = 0; mt < 2; mt++)
#pragma unroll
            for (int ks = 0; ks < 2; ks++)
                LDSM4(ah[mt][ks], aBase + mt * (16*80) + ks * 32);
#pragma unroll
        for (int nt = 0; nt < NT; nt++) {
            uint32_t bh[4], bl[4];
            LDSM4(bh, bS + nt * (8*144));
            LDSM4(bl, bS + nt * (8*144) + 64);
#pragma unroll
            for (int mt = 0; mt < 2; mt++) {
                MMA16816(acc[mt][nt], ah[mt][0], bh[0], bh[1]);
                MMA16816(acc[mt][nt], ah[mt][1], bh[2], bh[3]);
                MMA16816(acc[mt][nt], ah[mt][0], bl[0], bl[1]);
                MMA16816(acc[mt][nt], ah[mt][1], bl[2], bl[3]);
            }
        }
    }

    const float inv = rsqrtf(1.f + 1e-5f);
    const size_t S3 = (size_t)SOUT * SOUT * SOUT;
#pragma unroll
    for (int half = 0; half < NB / 64; half++) {
        __syncthreads();
#pragma unroll
        for (int nt2 = 0; nt2 < 8; nt2++) {
            int nt = half * 8 + nt2;
#pragma unroll
            for (int mt = 0; mt < 2; mt++) {
                int vr0 = w * 32 + mt * 16 + g, vr1 = vr0 + 8;
                int co = nt2 * 8 + 2 * tg;
                sT[co * 132 + vr0]       = acc[mt][nt][0];
                sT[(co + 1) * 132 + vr0] = acc[mt][nt][1];
                sT[co * 132 + vr1]       = acc[mt][nt][2];
                sT[(co + 1) * 132 + vr1] = acc[mt][nt][3];
            }
        }
        __syncthreads();
        for (int co = 0; co < 64; co++) {
            int cog = oc0 + half * 64 + co;
            float sc = gamma[cog] * inv, bb = beta[cog];
            float val = fmaxf(sT[co * 132 + tid] * sc + bb, 0.f);
            if (F32OUT)
                ((float*)out)[(size_t)cog * S3 + vbase + tid] = val;
            else
                ((__half*)out)[(size_t)cog * S3 + vbase + tid] = __float2half_rn(val);
        }
    }
}

// ---------------------------------------------------------------- fp32 L1 (stride-1, CI=4) -> fp16 out
template<int CI, int TY, int TXT>
__global__ void __launch_bounds__(128, 4)
conv_s1_db_kernel(const float* __restrict__ in, const float* __restrict__ wgt,
                  const float* __restrict__ gamma, const float* __restrict__ beta,
                  __half* __restrict__ out, int Sin, int Sout)
{
    constexpr int TZ = 4, XPT = 8;
    constexpr int TXO = TXT * XPT;
    constexpr int HZ = TZ + 2, HY = TY + 2, HXO = TXO + 2;
    constexpr int HTOT = HZ * HY * HXO;
    constexpr int ITERS = (HTOT + 127) / 128;

    __shared__ int s_off[HTOT];
    __shared__ float s_in[2][HTOT];
    __shared__ __align__(16) float s_w[2][216];

    const int tid = threadIdx.x;
    const int lx = tid % TXT;
    const int ly = (tid / TXT) % TY;
    const int lz = tid / (TXT * TY);

    const int ntx = Sout / TXO, nty = Sout / TY;
    int bt = blockIdx.x;
    const int tx0 = (bt % ntx) * TXO; bt /= ntx;
    const int ty0 = (bt % nty) * TY;  bt /= nty;
    const int tz0 = bt * TZ;
    const int oc0 = blockIdx.y * 8;

    const int bz = tz0 - 1, by = ty0 - 1, bx = tx0 - 1;

    for (int idx = tid; idx < HTOT; idx += 128) {
        int iz = idx / (HY * HXO);
        int rem = idx - iz * (HY * HXO);
        int iy = rem / HXO;
        int ix = rem - iy * HXO;
        int gz = bz + iz, gy = by + iy, gx = bx + ix;
        int off = -1;
        if ((unsigned)gz < (unsigned)Sin && (unsigned)gy < (unsigned)Sin &&
            (unsigned)gx < (unsigned)Sin)
            off = (gz * Sin + gy) * Sin + gx;
        s_off[idx] = off;
    }

    const float* wp0 = nullptr; const float* wp1 = nullptr;
    {
        int t0 = tid >> 3, o0 = tid & 7;
        wp0 = wgt + ((size_t)(oc0 + o0) * CI) * 27 + t0;
        int i1 = tid + 128;
        if (i1 < 216) {
            int t1 = i1 >> 3, o1 = i1 & 7;
            wp1 = wgt + ((size_t)(oc0 + o1) * CI) * 27 + t1;
        }
    }
    __syncthreads();

    const size_t Sin3 = (size_t)Sin * Sin * Sin;
    unsigned sin_base = (unsigned)__cvta_generic_to_shared(&s_in[0][0]);
    unsigned sw_base  = (unsigned)__cvta_generic_to_shared(&s_w[0][0]);

    {
        const float* inc = in;
#pragma unroll
        for (int k = 0; k < ITERS; k++) {
            int idx = tid + k * 128;
            if (idx < HTOT) {
                int o = s_off[idx];
                cp4(sin_base + idx * 4, inc + (o >= 0 ? o : 0), o >= 0 ? 4u : 0u);
            }
        }
        cp4(sw_base + tid * 4, wp0, 4u);
        if (wp1) cp4(sw_base + (tid + 128) * 4, wp1, 4u);
        cp_commit();
    }

    ull acc[XPT][4];
#pragma unroll
    for (int i = 0; i < XPT; i++)
#pragma unroll
        for (int p = 0; p < 4; p++) acc[i][p] = 0ULL;

    const int iz0 = lz, iy0 = ly, ixb = lx * XPT;

    for (int ci = 0; ci < CI; ci++) {
        cp_wait0();
        __syncthreads();

        const int cur = ci & 1, nxt = cur ^ 1;
        if (ci + 1 < CI) {
            const float* inc = in + (size_t)(ci + 1) * Sin3;
            unsigned dstb = sin_base + nxt * (HTOT * 4);
#pragma unroll
            for (int k = 0; k < ITERS; k++) {
                int idx = tid + k * 128;
                if (idx < HTOT) {
                    int o = s_off[idx];
                    cp4(dstb + idx * 4, inc + (o >= 0 ? o : 0), o >= 0 ? 4u : 0u);
                }
            }
            unsigned dw = sw_base + nxt * (216 * 4);
            cp4(dw + tid * 4, wp0 + (ci + 1) * 27, 4u);
            if (wp1) cp4(dw + (tid + 128) * 4, wp1 + (ci + 1) * 27, 4u);
            cp_commit();
        } else {
            cp_commit();
        }

        const float* sbuf = &s_in[cur][0];
        const float* swb  = &s_w[cur][0];

#pragma unroll
        for (int dz = 0; dz < 3; dz++) {
#pragma unroll
            for (int dy = 0; dy < 3; dy++) {
                const float* row = &sbuf[((iz0 + dz) * HY + (iy0 + dy)) * HXO + ixb];
                ull vvp[10];
#pragma unroll
                for (int j = 0; j < 10; j++) { float r = row[j]; PACK2(vvp[j], r); }
#pragma unroll
                for (int dx = 0; dx < 3; dx++) {
                    const ull* wp = (const ull*)&swb[((dz * 3 + dy) * 3 + dx) * 8];
                    const ull w0 = wp[0], w1 = wp[1], w2 = wp[2], w3 = wp[3];
#pragma unroll
                    for (int xi = 0; xi < XPT; xi++) {
                        const ull vx = vvp[xi + dx];
                        FMA2(acc[xi][0], vx, w0, acc[xi][0]);
                        FMA2(acc[xi][1], vx, w1, acc[xi][1]);
                        FMA2(acc[xi][2], vx, w2, acc[xi][2]);
                        FMA2(acc[xi][3], vx, w3, acc[xi][3]);
                    }
                }
            }
        }
        __syncthreads();
    }

    const int oz = tz0 + lz, oy = ty0 + ly, ox0 = tx0 + lx * XPT;
    const float inv = rsqrtf(1.f + 1e-5f);
    const size_t S3 = (size_t)Sout * Sout * Sout;
    const size_t sp = ((size_t)oz * Sout + oy) * Sout + ox0;
#pragma unroll
    for (int p = 0; p < 4; p++) {
        const int ocA = oc0 + 2 * p, ocB = ocA + 1;
        const float sA = gamma[ocA] * inv, bA = beta[ocA];
        const float sB = gamma[ocB] * inv, bB = beta[ocB];
        float lo[XPT], hi[XPT];
#pragma unroll
        for (int xi = 0; xi < XPT; xi++) {
            UNPACK2(lo[xi], hi[xi], acc[xi][p]);
            lo[xi] = fmaxf(lo[xi] * sA + bA, 0.f);
            hi[xi] = fmaxf(hi[xi] * sB + bB, 0.f);
        }
        uint4 va, vb;
        va.x = packh2(lo[0], lo[1]); va.y = packh2(lo[2], lo[3]);
        va.z = packh2(lo[4], lo[5]); va.w = packh2(lo[6], lo[7]);
        vb.x = packh2(hi[0], hi[1]); vb.y = packh2(hi[2], hi[3]);
        vb.z = packh2(hi[4], hi[5]); vb.w = packh2(hi[6], hi[7]);
        *(uint4*)(out + (size_t)ocA * S3 + sp) = va;
        *(uint4*)(out + (size_t)ocB * S3 + sp) = vb;
    }
}

// ---------------------------------------------------------------- BEV max + resize
__global__ void bevmax_kernel(const float* __restrict__ feat, float* __restrict__ bev) {
    int i = blockIdx.x * blockDim.x + threadIdx.x;
    if (i >= 256 * 32 * 32) return;
    int x = i & 31;
    int z = (i >> 5) & 31;
    int c = i >> 10;
    const float* p = feat + (((size_t)c * 32 + z) * 32) * 32 + x;
    float m = p[0];
#pragma unroll
    for (int y = 1; y < 32; y++) m = fmaxf(m, p[y * 32]);
    bev[i] = m;
}

__global__ void resize_kernel(const float* __restrict__ bev, float* __restrict__ out) {
    int i = blockIdx.x * blockDim.x + threadIdx.x;
    if (i >= 256 * 200 * 200) return;
    int ox = i % 200;
    int t  = i / 200;
    int oy = t % 200;
    int c  = t / 200;
    const float scale = 32.f / 200.f;
    float sy = (oy + 0.5f) * scale - 0.5f;
    float sx = (ox + 0.5f) * scale - 0.5f;
    int y0f = (int)floorf(sy); float fy = sy - (float)y0f;
    int x0f = (int)floorf(sx); float fx = sx - (float)x0f;
    int y0 = min(max(y0f, 0), 31), y1 = min(max(y0f + 1, 0), 31);
    int x0 = min(max(x0f, 0), 31), x1 = min(max(x0f + 1, 0), 31);
    const float* b = bev + (size_t)c * 1024;
    float v00 = b[y0 * 32 + x0], v01 = b[y0 * 32 + x1];
    float v10 = b[y1 * 32 + x0], v11 = b[y1 * 32 + x1];
    float v0 = v00 + (v01 - v00) * fx;
    float v1 = v10 + (v11 - v10) * fx;
    out[i] = v0 + (v1 - v0) * fy;
}

// ---------------------------------------------------------------- launch
extern "C" void kernel_launch(void* const* d_in, const int* in_sizes, int n_in,
                              void* d_out, int out_size) {
    const float* points = (const float*)d_in[0];
    const float* w[6]; const float* gm[6]; const float* bt[6];

    if (n_in >= 4 && in_sizes[2] == in_sizes[3] && in_sizes[2] <= 1024) {
        for (int i = 0; i < 6; i++) {
            w[i]  = (const float*)d_in[1 + 3*i];
            gm[i] = (const float*)d_in[2 + 3*i];
            bt[i] = (const float*)d_in[3 + 3*i];
        }
    } else {
        for (int i = 0; i < 6; i++) {
            w[i]  = (const float*)d_in[1 + i];
            gm[i] = (const float*)d_in[7 + i];
            bt[i] = (const float*)d_in[13 + i];
        }
    }
    const int N = in_sizes[0] / 4;

    float *A, *B; __half* W;
    cudaGetSymbolAddress((void**)&A, g_bufA);
    cudaGetSymbolAddress((void**)&B, g_bufB);
    cudaGetSymbolAddress((void**)&W, g_bufW);
    __half* Ah = (__half*)A;
    __half* Bh = (__half*)B;

    const int SM_L2 = ConvSm<2, 64, 64>::TOTAL;
    const int SM_L3 = ConvSm<1, 64, 64>::TOTAL;
    const int SM_L4 = ConvSm<2, 64, 32>::TOTAL;
    const int SM_L5 = ConvSm<1, 64, 32>::TOTAL;
    static bool attr_done = false;
    if (!attr_done) {
        cudaFuncSetAttribute(conv_mma_kernel< 32, 2, 64, 64, false>, cudaFuncAttributeMaxDynamicSharedMemorySize, SM_L2);
        cudaFuncSetAttribute(conv_mma_kernel< 64, 1, 64, 64, false>, cudaFuncAttributeMaxDynamicSharedMemorySize, SM_L3);
        cudaFuncSetAttribute(conv_mma_kernel< 64, 2, 64, 32, false>, cudaFuncAttributeMaxDynamicSharedMemorySize, SM_L4);
        cudaFuncSetAttribute(conv_mma_kernel<128, 1, 64, 32, false>, cudaFuncAttributeMaxDynamicSharedMemorySize, SM_L5);
        cudaFuncSetAttribute(conv_mma_kernel<128, 1, 64, 32, true >, cudaFuncAttributeMaxDynamicSharedMemorySize, SM_L5);
        attr_done = true;
    }

    // fused weight prep (hi/lo fp16 split)
    prep_all_kernel<<<496, 128>>>(w[1], w[2], w[3], w[4], w[5], W);
    __half* W2 = W;
    __half* W3 = W + 131072;
    __half* W4 = W + 393216;
    __half* W5 = W + 917504;
    __half* W6 = W + 1966080;

    // 1. voxelize into A (4,128^3) fp32
    const int gridElems = 4 * G3;
    zero_kernel<<<(gridElems + 255) / 256, 256>>>(A, gridElems);
    voxelize_kernel<<<(N + 255) / 256, 256>>>((const float4*)points, A, N);

    // 2. conv stack (fp16 activations between layers)
    // L1 fp32 in -> fp16 out: 4->32 s1 @128^3, A -> B
    { dim3 gr(2 * 32 * 32, 4); conv_s1_db_kernel<4, 4, 8><<<gr, 128>>>(A, w[0], gm[0], bt[0], Bh, 128, 128); }
    // L2: 32->64 s2 -> 64^3, B -> A
    { dim3 gr(2048, 1); conv_mma_kernel< 32, 2, 64, 64, false><<<gr, 128, SM_L2>>>(Bh, W2, gm[1], bt[1], Ah, 128,  64); }
    // L3: 64->64 s1 @64^3, A -> B
    { dim3 gr(2048, 1); conv_mma_kernel< 64, 1, 64, 64, false><<<gr, 128, SM_L3>>>(Ah, W3, gm[2], bt[2], Bh,  64,  64); }
    // L4: 64->128 s2 -> 32^3, B -> A  (NB=64, gridy=2 -> 512 blocks)
    { dim3 gr( 256, 2); conv_mma_kernel< 64, 2, 64, 32, false><<<gr, 128, SM_L4>>>(Bh, W4, gm[3], bt[3], Ah,  64, 128); }
    // L5: 128->128 s1 @32^3, A -> B  (NB=64, gridy=2 -> 512 blocks)
    { dim3 gr( 256, 2); conv_mma_kernel<128, 1, 64, 32, false><<<gr, 128, SM_L5>>>(Ah, W5, gm[4], bt[4], Bh,  32, 128); }
    // L6: 128->256 s1 @32^3, B -> A (fp32 out)  (NB=64, gridy=4 -> 1024 blocks)
    { dim3 gr( 256, 4); conv_mma_kernel<128, 1, 64, 32, true ><<<gr, 128, SM_L5>>>(Bh, W6, gm[5], bt[5], A,  32, 256); }

    // 3. BEV max over y: A (256,32,32,32) -> B (256,32,32)
    bevmax_kernel<<<(256 * 32 * 32 + 255) / 256, 256>>>(A, B);

    // 4. bilinear resize to (256,200,200)
    resize_kernel<<<(256 * 200 * 200 + 255) / 256, 256>>>(B, (float*)d_out);
}

// round 15
// speedup vs baseline: 1.6941x; 1.6941x over previous
#include <cuda_runtime.h>
#include <cuda_fp16.h>
#include <math.h>
#include <stdint.h>

#define G 128
#define G3 (G*G*G)

typedef unsigned long long ull;

// ---------------- packed f32x2 helpers (fp32 L1 kernel) ----------------
#define FMA2(d, a, b, c) \
    asm("fma.rn.f32x2 %0, %1, %2, %3;" : "=l"(d) : "l"(a), "l"(b), "l"(c))
#define PACK2(d, x) \
    asm("mov.b64 %0, {%1, %2};" : "=l"(d) : "r"(__float_as_uint(x)), "r"(__float_as_uint(x)))
#define UNPACK2(lo, hi, v) \
    asm("mov.b64 {%0, %1}, %2;" : "=f"(lo), "=f"(hi) : "l"(v))

__device__ __forceinline__ void cp4(unsigned dst, const void* src, unsigned sz) {
    asm volatile("cp.async.ca.shared.global [%0], [%1], 4, %2;" :: "r"(dst), "l"(src), "r"(sz));
}
__device__ __forceinline__ void cp16(unsigned dst, const void* src) {
    asm volatile("cp.async.cg.shared.global [%0], [%1], 16;" :: "r"(dst), "l"(src));
}
__device__ __forceinline__ void cp_commit() { asm volatile("cp.async.commit_group;"); }
__device__ __forceinline__ void cp_wait0() { asm volatile("cp.async.wait_group 0;"); }

// m16n8k16 fp16 MMA, f32 accumulate
#define MMA16816(d, a, b0v, b1v) \
    asm volatile("mma.sync.aligned.m16n8k16.row.col.f32.f16.f16.f32 " \
        "{%0,%1,%2,%3}, {%4,%5,%6,%7}, {%8,%9}, {%0,%1,%2,%3};" \
        : "+f"((d)[0]), "+f"((d)[1]), "+f"((d)[2]), "+f"((d)[3]) \
        : "r"((a)[0]), "r"((a)[1]), "r"((a)[2]), "r"((a)[3]), \
          "r"(b0v), "r"(b1v))

#define LDSM4(r, addr) \
    asm volatile("ldmatrix.sync.aligned.m8n8.x4.shared.b16 {%0,%1,%2,%3}, [%4];" \
        : "=r"((r)[0]), "=r"((r)[1]), "=r"((r)[2]), "=r"((r)[3]) : "r"(addr))

__device__ __forceinline__ uint32_t packh2(float a, float b) {
    __half2 h = __floats2half2_rn(a, b);
    return *(uint32_t*)&h;
}

// ---------------- scratch buffers ----------------
__device__ float g_bufA[16777216];     // 67MB
__device__ float g_bufB[67108864];     // 268MB
__device__ __half g_bufW[4063232];     // split fp16 weights

// ---------------------------------------------------------------- utilities
__global__ void zero_kernel(float* __restrict__ p, int n) {
    int i = blockIdx.x * blockDim.x + threadIdx.x;
    if (i < n) p[i] = 0.f;
}

// ---------------------------------------------------------------- voxelize
__global__ void voxelize_kernel(const float4* __restrict__ pts, float* __restrict__ grid, int N) {
    int i = blockIdx.x * blockDim.x + threadIdx.x;
    if (i >= N) return;
    float4 p = pts[i];
    if (p.x < -32.f || p.x > 32.f ||
        p.y < -32.f || p.y > 32.f ||
        p.z < -32.f || p.z > 32.f) return;
    int cx = (int)floorf((p.x + 32.f) * 2.f);
    int cy = (int)floorf((p.y + 32.f) * 2.f);
    int cz = (int)floorf((p.z + 32.f) * 2.f);
    cx = cx < 0 ? 0 : (cx > G-1 ? G-1 : cx);
    cy = cy < 0 ? 0 : (cy > G-1 ? G-1 : cy);
    cz = cz < 0 ? 0 : (cz > G-1 ? G-1 : cz);
    int base = (cz * G + cy) * G + cx;
    atomicAdd(&grid[0*G3 + base], p.x);
    atomicAdd(&grid[1*G3 + base], p.y);
    atomicAdd(&grid[2*G3 + base], p.z);
    atomicAdd(&grid[3*G3 + base], p.w);
}

// ---------------------------------------------------------------- fused weight prep (hi/lo fp16)
__global__ void prep_all_kernel(const float* __restrict__ w2, const float* __restrict__ w3,
                                const float* __restrict__ w4, const float* __restrict__ w5,
                                const float* __restrict__ w6, __half* __restrict__ dst) {
    int idx = blockIdx.x * blockDim.x + threadIdx.x;
    const float* w; int CO, CI; size_t off;
    if (idx < 2048)                  { w = w2; CO =  64; CI =  32; off = 0; }
    else if ((idx -= 2048) < 4096)   { w = w3; CO =  64; CI =  64; off = 131072; }
    else if ((idx -= 4096) < 8192)   { w = w4; CO = 128; CI =  64; off = 393216; }
    else if ((idx -= 8192) < 16384)  { w = w5; CO = 128; CI = 128; off = 917504; }
    else if ((idx -= 16384) < 32768) { w = w6; CO = 256; CI = 128; off = 1966080; }
    else return;
    int ci = idx / CO, co = idx - ci * CO;
    const float* ws = w + ((size_t)co * CI + ci) * 27;

    uint32_t h2[16], l2[16];
#pragma unroll
    for (int p = 0; p < 13; p++) {
        float a = ws[2*p], b = ws[2*p+1];
        __half2 h = __floats2half2_rn(a, b);
        float2 hf = __half22float2(h);
        h2[p] = *(uint32_t*)&h;
        l2[p] = packh2(a - hf.x, b - hf.y);
    }
    {
        float a = ws[26];
        __half ha = __float2half_rn(a);
        __half2 h = __halves2half2(ha, __ushort_as_half(0));
        h2[13] = *(uint32_t*)&h;
        l2[13] = packh2(a - __half2float(ha), 0.f);
        h2[14] = h2[15] = l2[14] = l2[15] = 0u;
    }
    uint4* o = (uint4*)(dst + off + (size_t)(ci * CO + co) * 64);
    o[0] = make_uint4(h2[0], h2[1], h2[2], h2[3]);
    o[1] = make_uint4(h2[4], h2[5], h2[6], h2[7]);
    o[2] = make_uint4(h2[8], h2[9], h2[10], h2[11]);
    o[3] = make_uint4(h2[12], h2[13], h2[14], h2[15]);
    o[4] = make_uint4(l2[0], l2[1], l2[2], l2[3]);
    o[5] = make_uint4(l2[4], l2[5], l2[6], l2[7]);
    o[6] = make_uint4(l2[8], l2[9], l2[10], l2[11]);
    o[7] = make_uint4(l2[12], l2[13], l2[14], l2[15]);
}

// ---------------------------------------------------------------- smem size helpers
__host__ __device__ constexpr int align16(int x) { return (x + 15) & ~15; }
__host__ __device__ constexpr int cmax(int a, int b) { return a > b ? a : b; }

template<int STRIDE, int NB, int SOUT>
struct ConvSm {
    static constexpr int TYO  = 128 / SOUT;
    static constexpr int HX   = (SOUT - 1) * STRIDE + 3;
    static constexpr int HY   = (TYO - 1) * STRIDE + 3;
    static constexpr int PX   = (HX + 2) / 2;
    static constexpr int HTOTP = 3 * HY * PX;
    static constexpr int TBLB = align16(HTOTP * 4);
    static constexpr int TILEB = align16(HTOTP * 4);
    static constexpr int A_OFF = TBLB + 2 * TILEB;
    static constexpr int B_OFF = A_OFF + 128 * 80;
    static constexpr int TOTAL = cmax(B_OFF + 2 * NB * 144, 64 * 132 * 4);
};

// ---------------------------------------------------------------- mma implicit-GEMM conv (R11)
template<int CI, int STRIDE, int NB, int SOUT, bool F32OUT>
__global__ void __launch_bounds__(128)
conv_mma_kernel(const __half* __restrict__ in, const __half* __restrict__ Wp,
                const float* __restrict__ gamma, const float* __restrict__ beta,
                void* __restrict__ out, int Sin, int CO)
{
    using SM = ConvSm<STRIDE, NB, SOUT>;
    constexpr int NT = NB / 8;
    constexpr int HY = SM::HY, PX = SM::PX, HTOTP = SM::HTOTP;
    constexpr int TYO = SM::TYO;

    extern __shared__ __align__(16) char sm[];
    int* tbl = (int*)sm;
    char* sA = sm + SM::A_OFF;
    float* sT = (float*)sm;

    const int tid = threadIdx.x;
    const int w = tid >> 5, lane = tid & 31;
    const int g = lane >> 2, tg = lane & 3;

    const uint32_t uTile = (uint32_t)__cvta_generic_to_shared(sm + SM::TBLB);
    const uint32_t uA = (uint32_t)__cvta_generic_to_shared(sA);
    const uint32_t uB = (uint32_t)__cvta_generic_to_shared(sm + SM::B_OFF);
    const uint32_t aBase = uA + (uint32_t)((w * 32 + (lane & 15)) * 80 + (lane >> 4) * 16);
    const uint32_t bBase = uB + (uint32_t)((lane & 7) * 144 + (lane >> 3) * 16);

    const int nby = SOUT / TYO;
    const int bz = blockIdx.x / nby;
    const int by0 = (blockIdx.x % nby) * TYO;
    const int oc0 = blockIdx.y * NB;
    const int vbase = blockIdx.x * 128;

    const int y = tid / SOUT, x = tid % SOUT;
    const int oz = bz * STRIDE - 1, oy = by0 * STRIDE - 1;
    const size_t SinSq = (size_t)Sin * Sin;
    const size_t Sin3 = SinSq * Sin;
    const uint32_t* inu = (const uint32_t*)in;

    for (int idx = tid; idx < HTOTP; idx += 128) {
        int tz = idx / (HY * PX);
        int rem = idx - tz * (HY * PX);
        int ty = rem / PX;
        int px = rem - ty * PX;
        int gz = oz + tz, gy = oy + ty, gx0 = px * 2 - 2;
        int off = -1;
        if ((unsigned)gz < (unsigned)Sin && (unsigned)gy < (unsigned)Sin &&
            gx0 >= 0 && gx0 <= Sin - 2)
            off = (int)(((size_t)gz * SinSq + (size_t)gy * Sin + gx0) >> 1);
        tbl[idx] = off;
    }
    __syncthreads();

    float acc[2][NT][4];
#pragma unroll
    for (int mt = 0; mt < 2; mt++)
#pragma unroll
        for (int nt = 0; nt < NT; nt++)
#pragma unroll
            for (int q = 0; q < 4; q++) acc[mt][nt][q] = 0.f;

    {
        for (int idx = tid; idx < HTOTP; idx += 128) {
            int o = tbl[idx];
            cp4(uTile + idx * 4, inu + (o >= 0 ? o : 0), o >= 0 ? 4u : 0u);
        }
        const char* srcb = (const char*)(Wp + ((size_t)oc0) * 64);
        for (int u = tid; u < NB * 8; u += 128) {
            int co = u >> 3, seg = u & 7;
            cp16(uB + co * 144 + seg * 16, srcb + co * 128 + seg * 16);
        }
        cp_commit();
    }

    for (int ci = 0; ci < CI; ci++) {
        const int s = ci & 1;
        cp_wait0();
        __syncthreads();

        if (ci + 1 < CI) {
            const uint32_t* basep = inu + ((size_t)(ci + 1) * Sin3 >> 1);
            const uint32_t td = uTile + (s ^ 1) * SM::TILEB;
            for (int idx = tid; idx < HTOTP; idx += 128) {
                int o = tbl[idx];
                cp4(td + idx * 4, basep + (o >= 0 ? o : 0), o >= 0 ? 4u : 0u);
            }
            const char* srcb = (const char*)(Wp + ((size_t)(ci + 1) * CO + oc0) * 64);
            const uint32_t bd = uB + (s ^ 1) * (NB * 144);
            for (int u = tid; u < NB * 8; u += 128) {
                int co = u >> 3, seg = u & 7;
                cp16(bd + co * 144 + seg * 16, srcb + co * 128 + seg * 16);
            }
            cp_commit();
        }

        {
            const unsigned short* tp =
                (const unsigned short*)(sm + SM::TBLB + s * SM::TILEB);
            unsigned short t[27];
#pragma unroll
            for (int dz = 0; dz < 3; dz++)
#pragma unroll
                for (int dy = 0; dy < 3; dy++) {
                    const unsigned short* r =
                        tp + (dz * HY + y * STRIDE + dy) * (2 * PX) + x * STRIDE + 1;
                    t[(dz*3+dy)*3 + 0] = r[0];
                    t[(dz*3+dy)*3 + 1] = r[1];
                    t[(dz*3+dy)*3 + 2] = r[2];
                }
            uint32_t h2[16];
#pragma unroll
            for (int j = 0; j < 13; j++)
                h2[j] = (uint32_t)t[2*j] | ((uint32_t)t[2*j+1] << 16);
            h2[13] = (uint32_t)t[26];
            h2[14] = h2[15] = 0u;
            uint4* rowp = (uint4*)(sA + tid * 80);
            rowp[0] = make_uint4(h2[0], h2[1], h2[2], h2[3]);
            rowp[1] = make_uint4(h2[4], h2[5], h2[6], h2[7]);
            rowp[2] = make_uint4(h2[8], h2[9], h2[10], h2[11]);
            rowp[3] = make_uint4(h2[12], h2[13], h2[14], h2[15]);
        }
        __syncwarp();

        const uint32_t bS = bBase + s * (NB * 144);
        uint32_t ah[2][2][4];
#pragma unroll
        for (int mt = 0; mt < 2; mt++)
#pragma unroll
            for (int ks = 0; ks < 2; ks++)
                LDSM4(ah[mt][ks], aBase + mt * (16*80) + ks * 32);
#pragma unroll
        for (int nt = 0; nt < NT; nt++) {
            uint32_t bh[4], bl[4];
            LDSM4(bh, bS + nt * (8*144));
            LDSM4(bl, bS + nt * (8*144) + 64);
#pragma unroll
            for (int mt = 0; mt < 2; mt++) {
                MMA16816(acc[mt][nt], ah[mt][0], bh[0], bh[1]);
                MMA16816(acc[mt][nt], ah[mt][1], bh[2], bh[3]);
                MMA16816(acc[mt][nt], ah[mt][0], bl[0], bl[1]);
                MMA16816(acc[mt][nt], ah[mt][1], bl[2], bl[3]);
            }
        }
    }

    const float inv = rsqrtf(1.f + 1e-5f);
    const size_t S3 = (size_t)SOUT * SOUT * SOUT;
#pragma unroll
    for (int half = 0; half < NB / 64; half++) {
        __syncthreads();
#pragma unroll
        for (int nt2 = 0; nt2 < 8; nt2++) {
            int nt = half * 8 + nt2;
#pragma unroll
            for (int mt = 0; mt < 2; mt++) {
                int vr0 = w * 32 + mt * 16 + g, vr1 = vr0 + 8;
                int co = nt2 * 8 + 2 * tg;
                sT[co * 132 + vr0]       = acc[mt][nt][0];
                sT[(co + 1) * 132 + vr0] = acc[mt][nt][1];
                sT[co * 132 + vr1]       = acc[mt][nt][2];
                sT[(co + 1) * 132 + vr1] = acc[mt][nt][3];
            }
        }
        __syncthreads();
        for (int co = 0; co < 64; co++) {
            int cog = oc0 + half * 64 + co;
            float sc = gamma[cog] * inv, bb = beta[cog];
            float val = fmaxf(sT[co * 132 + tid] * sc + bb, 0.f);
            if (F32OUT)
                ((float*)out)[(size_t)cog * S3 + vbase + tid] = val;
            else
                ((__half*)out)[(size_t)cog * S3 + vbase + tid] = __float2half_rn(val);
        }
    }
}

// ---------------------------------------------------------------- fp32 L1 (stride-1, CI=4) -> fp16 out
template<int CI, int TY, int TXT>
__global__ void __launch_bounds__(128, 4)
conv_s1_db_kernel(const float* __restrict__ in, const float* __restrict__ wgt,
                  const float* __restrict__ gamma, const float* __restrict__ beta,
                  __half* __restrict__ out, int Sin, int Sout)
{
    constexpr int TZ = 4, XPT = 8;
    constexpr int TXO = TXT * XPT;
    constexpr int HZ = TZ + 2, HY = TY + 2, HXO = TXO + 2;
    constexpr int HTOT = HZ * HY * HXO;
    constexpr int ITERS = (HTOT + 127) / 128;

    __shared__ int s_off[HTOT];
    __shared__ float s_in[2][HTOT];
    __shared__ __align__(16) float s_w[2][216];

    const int tid = threadIdx.x;
    const int lx = tid % TXT;
    const int ly = (tid / TXT) % TY;
    const int lz = tid / (TXT * TY);

    const int ntx = Sout / TXO, nty = Sout / TY;
    int bt = blockIdx.x;
    const int tx0 = (bt % ntx) * TXO; bt /= ntx;
    const int ty0 = (bt % nty) * TY;  bt /= nty;
    const int tz0 = bt * TZ;
    const int oc0 = blockIdx.y * 8;

    const int bz = tz0 - 1, by = ty0 - 1, bx = tx0 - 1;

    for (int idx = tid; idx < HTOT; idx += 128) {
        int iz = idx / (HY * HXO);
        int rem = idx - iz * (HY * HXO);
        int iy = rem / HXO;
        int ix = rem - iy * HXO;
        int gz = bz + iz, gy = by + iy, gx = bx + ix;
        int off = -1;
        if ((unsigned)gz < (unsigned)Sin && (unsigned)gy < (unsigned)Sin &&
            (unsigned)gx < (unsigned)Sin)
            off = (gz * Sin + gy) * Sin + gx;
        s_off[idx] = off;
    }

    const float* wp0 = nullptr; const float* wp1 = nullptr;
    {
        int t0 = tid >> 3, o0 = tid & 7;
        wp0 = wgt + ((size_t)(oc0 + o0) * CI) * 27 + t0;
        int i1 = tid + 128;
        if (i1 < 216) {
            int t1 = i1 >> 3, o1 = i1 & 7;
            wp1 = wgt + ((size_t)(oc0 + o1) * CI) * 27 + t1;
        }
    }
    __syncthreads();

    const size_t Sin3 = (size_t)Sin * Sin * Sin;
    unsigned sin_base = (unsigned)__cvta_generic_to_shared(&s_in[0][0]);
    unsigned sw_base  = (unsigned)__cvta_generic_to_shared(&s_w[0][0]);

    {
        const float* inc = in;
#pragma unroll
        for (int k = 0; k < ITERS; k++) {
            int idx = tid + k * 128;
            if (idx < HTOT) {
                int o = s_off[idx];
                cp4(sin_base + idx * 4, inc + (o >= 0 ? o : 0), o >= 0 ? 4u : 0u);
            }
        }
        cp4(sw_base + tid * 4, wp0, 4u);
        if (wp1) cp4(sw_base + (tid + 128) * 4, wp1, 4u);
        cp_commit();
    }

    ull acc[XPT][4];
#pragma unroll
    for (int i = 0; i < XPT; i++)
#pragma unroll
        for (int p = 0; p < 4; p++) acc[i][p] = 0ULL;

    const int iz0 = lz, iy0 = ly, ixb = lx * XPT;

    for (int ci = 0; ci < CI; ci++) {
        cp_wait0();
        __syncthreads();

        const int cur = ci & 1, nxt = cur ^ 1;
        if (ci + 1 < CI) {
            const float* inc = in + (size_t)(ci + 1) * Sin3;
            unsigned dstb = sin_base + nxt * (HTOT * 4);
#pragma unroll
            for (int k = 0; k < ITERS; k++) {
                int idx = tid + k * 128;
                if (idx < HTOT) {
                    int o = s_off[idx];
                    cp4(dstb + idx * 4, inc + (o >= 0 ? o : 0), o >= 0 ? 4u : 0u);
                }
            }
            unsigned dw = sw_base + nxt * (216 * 4);
            cp4(dw + tid * 4, wp0 + (ci + 1) * 27, 4u);
            if (wp1) cp4(dw + (tid + 128) * 4, wp1 + (ci + 1) * 27, 4u);
            cp_commit();
        } else {
            cp_commit();
        }

        const float* sbuf = &s_in[cur][0];
        const float* swb  = &s_w[cur][0];

#pragma unroll
        for (int dz = 0; dz < 3; dz++) {
#pragma unroll
            for (int dy = 0; dy < 3; dy++) {
                const float* row = &sbuf[((iz0 + dz) * HY + (iy0 + dy)) * HXO + ixb];
                ull vvp[10];
#pragma unroll
                for (int j = 0; j < 10; j++) { float r = row[j]; PACK2(vvp[j], r); }
#pragma unroll
                for (int dx = 0; dx < 3; dx++) {
                    const ull* wp = (const ull*)&swb[((dz * 3 + dy) * 3 + dx) * 8];
                    const ull w0 = wp[0], w1 = wp[1], w2 = wp[2], w3 = wp[3];
#pragma unroll
                    for (int xi = 0; xi < XPT; xi++) {
                        const ull vx = vvp[xi + dx];
                        FMA2(acc[xi][0], vx, w0, acc[xi][0]);
                        FMA2(acc[xi][1], vx, w1, acc[xi][1]);
                        FMA2(acc[xi][2], vx, w2, acc[xi][2]);
                        FMA2(acc[xi][3], vx, w3, acc[xi][3]);
                    }
                }
            }
        }
        __syncthreads();
    }

    const int oz = tz0 + lz, oy = ty0 + ly, ox0 = tx0 + lx * XPT;
    const float inv = rsqrtf(1.f + 1e-5f);
    const size_t S3 = (size_t)Sout * Sout * Sout;
    const size_t sp = ((size_t)oz * Sout + oy) * Sout + ox0;
#pragma unroll
    for (int p = 0; p < 4; p++) {
        const int ocA = oc0 + 2 * p, ocB = ocA + 1;
        const float sA = gamma[ocA] * inv, bA = beta[ocA];
        const float sB = gamma[ocB] * inv, bB = beta[ocB];
        float lo[XPT], hi[XPT];
#pragma unroll
        for (int xi = 0; xi < XPT; xi++) {
            UNPACK2(lo[xi], hi[xi], acc[xi][p]);
            lo[xi] = fmaxf(lo[xi] * sA + bA, 0.f);
            hi[xi] = fmaxf(hi[xi] * sB + bB, 0.f);
        }
        uint4 va, vb;
        va.x = packh2(lo[0], lo[1]); va.y = packh2(lo[2], lo[3]);
        va.z = packh2(lo[4], lo[5]); va.w = packh2(lo[6], lo[7]);
        vb.x = packh2(hi[0], hi[1]); vb.y = packh2(hi[2], hi[3]);
        vb.z = packh2(hi[4], hi[5]); vb.w = packh2(hi[6], hi[7]);
        *(uint4*)(out + (size_t)ocA * S3 + sp) = va;
        *(uint4*)(out + (size_t)ocB * S3 + sp) = vb;
    }
}

// ---------------------------------------------------------------- BEV max (float4) + resize
__global__ void bevmax_kernel(const float* __restrict__ feat, float* __restrict__ bev) {
    int i = blockIdx.x * blockDim.x + threadIdx.x;
    if (i >= 256 * 32 * 8) return;
    int x4 = i & 7;
    int z = (i >> 3) & 31;
    int c = i >> 8;
    const float4* p = (const float4*)(feat + (((size_t)c * 32 + z) * 32) * 32) + x4;
    float4 m = p[0];
#pragma unroll
    for (int y = 1; y < 32; y++) {
        float4 v = p[y * 8];
        m.x = fmaxf(m.x, v.x); m.y = fmaxf(m.y, v.y);
        m.z = fmaxf(m.z, v.z); m.w = fmaxf(m.w, v.w);
    }
    ((float4*)bev)[i] = m;
}

__global__ void resize_kernel(const float* __restrict__ bev, float* __restrict__ out) {
    int i = blockIdx.x * blockDim.x + threadIdx.x;
    if (i >= 256 * 200 * 200) return;
    int ox = i % 200;
    int t  = i / 200;
    int oy = t % 200;
    int c  = t / 200;
    const float scale = 32.f / 200.f;
    float sy = (oy + 0.5f) * scale - 0.5f;
    float sx = (ox + 0.5f) * scale - 0.5f;
    int y0f = (int)floorf(sy); float fy = sy - (float)y0f;
    int x0f = (int)floorf(sx); float fx = sx - (float)x0f;
    int y0 = min(max(y0f, 0), 31), y1 = min(max(y0f + 1, 0), 31);
    int x0 = min(max(x0f, 0), 31), x1 = min(max(x0f + 1, 0), 31);
    const float* b = bev + (size_t)c * 1024;
    float v00 = b[y0 * 32 + x0], v01 = b[y0 * 32 + x1];
    float v10 = b[y1 * 32 + x0], v11 = b[y1 * 32 + x1];
    float v0 = v00 + (v01 - v00) * fx;
    float v1 = v10 + (v11 - v10) * fx;
    out[i] = v0 + (v1 - v0) * fy;
}

// ---------------------------------------------------------------- launch
extern "C" void kernel_launch(void* const* d_in, const int* in_sizes, int n_in,
                              void* d_out, int out_size) {
    const float* points = (const float*)d_in[0];
    const float* w[6]; const float* gm[6]; const float* bt[6];

    if (n_in >= 4 && in_sizes[2] == in_sizes[3] && in_sizes[2] <= 1024) {
        for (int i = 0; i < 6; i++) {
            w[i]  = (const float*)d_in[1 + 3*i];
            gm[i] = (const float*)d_in[2 + 3*i];
            bt[i] = (const float*)d_in[3 + 3*i];
        }
    } else {
        for (int i = 0; i < 6; i++) {
            w[i]  = (const float*)d_in[1 + i];
            gm[i] = (const float*)d_in[7 + i];
            bt[i] = (const float*)d_in[13 + i];
        }
    }
    const int N = in_sizes[0] / 4;

    float *A, *B; __half* W;
    cudaGetSymbolAddress((void**)&A, g_bufA);
    cudaGetSymbolAddress((void**)&B, g_bufB);
    cudaGetSymbolAddress((void**)&W, g_bufW);
    __half* Ah = (__half*)A;
    __half* Bh = (__half*)B;

    const int SM_L2 = ConvSm<2,  64, 64>::TOTAL;
    const int SM_L3 = ConvSm<1,  64, 64>::TOTAL;
    const int SM_L4 = ConvSm<2, 128, 32>::TOTAL;
    const int SM_L5 = ConvSm<1, 128, 32>::TOTAL;
    static bool attr_done = false;
    if (!attr_done) {
        cudaFuncSetAttribute(conv_mma_kernel< 32, 2,  64, 64, false>, cudaFuncAttributeMaxDynamicSharedMemorySize, SM_L2);
        cudaFuncSetAttribute(conv_mma_kernel< 64, 1,  64, 64, false>, cudaFuncAttributeMaxDynamicSharedMemorySize, SM_L3);
        cudaFuncSetAttribute(conv_mma_kernel< 64, 2, 128, 32, false>, cudaFuncAttributeMaxDynamicSharedMemorySize, SM_L4);
        cudaFuncSetAttribute(conv_mma_kernel<128, 1, 128, 32, false>, cudaFuncAttributeMaxDynamicSharedMemorySize, SM_L5);
        cudaFuncSetAttribute(conv_mma_kernel<128, 1, 128, 32, true >, cudaFuncAttributeMaxDynamicSharedMemorySize, SM_L5);
        attr_done = true;
    }

    // fused weight prep (hi/lo fp16 split)
    prep_all_kernel<<<496, 128>>>(w[1], w[2], w[3], w[4], w[5], W);
    __half* W2 = W;
    __half* W3 = W + 131072;
    __half* W4 = W + 393216;
    __half* W5 = W + 917504;
    __half* W6 = W + 1966080;

    // 1. voxelize into A (4,128^3) fp32
    const int gridElems = 4 * G3;
    zero_kernel<<<(gridElems + 255) / 256, 256>>>(A, gridElems);
    voxelize_kernel<<<(N + 255) / 256, 256>>>((const float4*)points, A, N);

    // 2. conv stack (fp16 activations between layers)
    // L1 fp32 in -> fp16 out: 4->32 s1 @128^3, A -> B
    { dim3 gr(2 * 32 * 32, 4); conv_s1_db_kernel<4, 4, 8><<<gr, 128>>>(A, w[0], gm[0], bt[0], Bh, 128, 128); }
    // L2: 32->64 s2 -> 64^3, B -> A
    { dim3 gr(2048, 1); conv_mma_kernel< 32, 2,  64, 64, false><<<gr, 128, SM_L2>>>(Bh, W2, gm[1], bt[1], Ah, 128,  64); }
    // L3: 64->64 s1 @64^3, A -> B
    { dim3 gr(2048, 1); conv_mma_kernel< 64, 1,  64, 64, false><<<gr, 128, SM_L3>>>(Ah, W3, gm[2], bt[2], Bh,  64,  64); }
    // L4: 64->128 s2 -> 32^3, B -> A
    { dim3 gr( 256, 1); conv_mma_kernel< 64, 2, 128, 32, false><<<gr, 128, SM_L4>>>(Bh, W4, gm[3], bt[3], Ah,  64, 128); }
    // L5: 128->128 s1 @32^3, A -> B
    { dim3 gr( 256, 1); conv_mma_kernel<128, 1, 128, 32, false><<<gr, 128, SM_L5>>>(Ah, W5, gm[4], bt[4], Bh,  32, 128); }
    // L6: 128->256 s1 @32^3, B -> A (fp32 out)
    { dim3 gr( 256, 2); conv_mma_kernel<128, 1, 128, 32, true ><<<gr, 128, SM_L5>>>(Bh, W6, gm[5], bt[5], A,  32, 256); }

    // 3. BEV max over y: A (256,32,32,32) -> B (256,32,32)  (float4)
    bevmax_kernel<<<(256 * 32 * 8 + 255) / 256, 256>>>(A, B);

    // 4. bilinear resize to (256,200,200)
    resize_kernel<<<(256 * 200 * 200 + 255) / 256, 256>>>(B, (float*)d_out);
}

// round 16
// speedup vs baseline: 1.6980x; 1.0023x over previous
#include <cuda_runtime.h>
#include <cuda_fp16.h>
#include <math.h>
#include <stdint.h>

#define G 128
#define G3 (G*G*G)

typedef unsigned long long ull;

// ---------------- packed f32x2 helpers (fp32 L1 kernel) ----------------
#define FMA2(d, a, b, c) \
    asm("fma.rn.f32x2 %0, %1, %2, %3;" : "=l"(d) : "l"(a), "l"(b), "l"(c))
#define PACK2(d, x) \
    asm("mov.b64 %0, {%1, %2};" : "=l"(d) : "r"(__float_as_uint(x)), "r"(__float_as_uint(x)))
#define UNPACK2(lo, hi, v) \
    asm("mov.b64 {%0, %1}, %2;" : "=f"(lo), "=f"(hi) : "l"(v))

__device__ __forceinline__ void cp4(unsigned dst, const void* src, unsigned sz) {
    asm volatile("cp.async.ca.shared.global [%0], [%1], 4, %2;" :: "r"(dst), "l"(src), "r"(sz));
}
__device__ __forceinline__ void cp16(unsigned dst, const void* src) {
    asm volatile("cp.async.cg.shared.global [%0], [%1], 16;" :: "r"(dst), "l"(src));
}
__device__ __forceinline__ void cp_commit() { asm volatile("cp.async.commit_group;"); }
__device__ __forceinline__ void cp_wait0() { asm volatile("cp.async.wait_group 0;"); }

// m16n8k16 fp16 MMA, f32 accumulate
#define MMA16816(d, a, b0v, b1v) \
    asm volatile("mma.sync.aligned.m16n8k16.row.col.f32.f16.f16.f32 " \
        "{%0,%1,%2,%3}, {%4,%5,%6,%7}, {%8,%9}, {%0,%1,%2,%3};" \
        : "+f"((d)[0]), "+f"((d)[1]), "+f"((d)[2]), "+f"((d)[3]) \
        : "r"((a)[0]), "r"((a)[1]), "r"((a)[2]), "r"((a)[3]), \
          "r"(b0v), "r"(b1v))

#define LDSM4(r, addr) \
    asm volatile("ldmatrix.sync.aligned.m8n8.x4.shared.b16 {%0,%1,%2,%3}, [%4];" \
        : "=r"((r)[0]), "=r"((r)[1]), "=r"((r)[2]), "=r"((r)[3]) : "r"(addr))

__device__ __forceinline__ uint32_t packh2(float a, float b) {
    __half2 h = __floats2half2_rn(a, b);
    return *(uint32_t*)&h;
}

// ---------------- scratch buffers ----------------
__device__ float g_bufA[16777216];     // 67MB
__device__ float g_bufB[67108864];     // 268MB
__device__ __half g_bufW[4063232];     // split fp16 weights

// ---------------------------------------------------------------- utilities
__global__ void zero_kernel(float* __restrict__ p, int n) {
    int i = blockIdx.x * blockDim.x + threadIdx.x;
    if (i < n) p[i] = 0.f;
}

// ---------------------------------------------------------------- voxelize
__global__ void voxelize_kernel(const float4* __restrict__ pts, float* __restrict__ grid, int N) {
    int i = blockIdx.x * blockDim.x + threadIdx.x;
    if (i >= N) return;
    float4 p = pts[i];
    if (p.x < -32.f || p.x > 32.f ||
        p.y < -32.f || p.y > 32.f ||
        p.z < -32.f || p.z > 32.f) return;
    int cx = (int)floorf((p.x + 32.f) * 2.f);
    int cy = (int)floorf((p.y + 32.f) * 2.f);
    int cz = (int)floorf((p.z + 32.f) * 2.f);
    cx = cx < 0 ? 0 : (cx > G-1 ? G-1 : cx);
    cy = cy < 0 ? 0 : (cy > G-1 ? G-1 : cy);
    cz = cz < 0 ? 0 : (cz > G-1 ? G-1 : cz);
    int base = (cz * G + cy) * G + cx;
    atomicAdd(&grid[0*G3 + base], p.x);
    atomicAdd(&grid[1*G3 + base], p.y);
    atomicAdd(&grid[2*G3 + base], p.z);
    atomicAdd(&grid[3*G3 + base], p.w);
}

// ---------------------------------------------------------------- fused weight prep (hi/lo fp16)
__global__ void prep_all_kernel(const float* __restrict__ w2, const float* __restrict__ w3,
                                const float* __restrict__ w4, const float* __restrict__ w5,
                                const float* __restrict__ w6, __half* __restrict__ dst) {
    int idx = blockIdx.x * blockDim.x + threadIdx.x;
    const float* w; int CO, CI; size_t off;
    if (idx < 2048)                  { w = w2; CO =  64; CI =  32; off = 0; }
    else if ((idx -= 2048) < 4096)   { w = w3; CO =  64; CI =  64; off = 131072; }
    else if ((idx -= 4096) < 8192)   { w = w4; CO = 128; CI =  64; off = 393216; }
    else if ((idx -= 8192) < 16384)  { w = w5; CO = 128; CI = 128; off = 917504; }
    else if ((idx -= 16384) < 32768) { w = w6; CO = 256; CI = 128; off = 1966080; }
    else return;
    int ci = idx / CO, co = idx - ci * CO;
    const float* ws = w + ((size_t)co * CI + ci) * 27;

    uint32_t h2[16], l2[16];
#pragma unroll
    for (int p = 0; p < 13; p++) {
        float a = ws[2*p], b = ws[2*p+1];
        __half2 h = __floats2half2_rn(a, b);
        float2 hf = __half22float2(h);
        h2[p] = *(uint32_t*)&h;
        l2[p] = packh2(a - hf.x, b - hf.y);
    }
    {
        float a = ws[26];
        __half ha = __float2half_rn(a);
        __half2 h = __halves2half2(ha, __ushort_as_half(0));
        h2[13] = *(uint32_t*)&h;
        l2[13] = packh2(a - __half2float(ha), 0.f);
        h2[14] = h2[15] = l2[14] = l2[15] = 0u;
    }
    uint4* o = (uint4*)(dst + off + (size_t)(ci * CO + co) * 64);
    o[0] = make_uint4(h2[0], h2[1], h2[2], h2[3]);
    o[1] = make_uint4(h2[4], h2[5], h2[6], h2[7]);
    o[2] = make_uint4(h2[8], h2[9], h2[10], h2[11]);
    o[3] = make_uint4(h2[12], h2[13], h2[14], h2[15]);
    o[4] = make_uint4(l2[0], l2[1], l2[2], l2[3]);
    o[5] = make_uint4(l2[4], l2[5], l2[6], l2[7]);
    o[6] = make_uint4(l2[8], l2[9], l2[10], l2[11]);
    o[7] = make_uint4(l2[12], l2[13], l2[14], l2[15]);
}

// ---------------------------------------------------------------- smem size helpers
__host__ __device__ constexpr int align16(int x) { return (x + 15) & ~15; }
__host__ __device__ constexpr int cmax(int a, int b) { return a > b ? a : b; }

template<int STRIDE, int NB, int SOUT>
struct ConvSm {
    static constexpr int TYO  = 128 / SOUT;
    static constexpr int HX   = (SOUT - 1) * STRIDE + 3;
    static constexpr int HY   = (TYO - 1) * STRIDE + 3;
    static constexpr int PX   = (HX + 2) / 2;
    static constexpr int HTOTP = 3 * HY * PX;
    static constexpr int TBLB = align16(HTOTP * 4);
    static constexpr int TILEB = align16(HTOTP * 4);
    static constexpr int A_OFF = TBLB + 2 * TILEB;
    static constexpr int B_OFF = A_OFF + 128 * 80;
    static constexpr int TOTAL = cmax(B_OFF + 2 * NB * 144, 64 * 132 * 4);
};

// ---------------------------------------------------------------- mma implicit-GEMM conv (R11)
// OUTMODE: 0 = fp16 store, 1 = fused BEV atomicMax (post-ReLU >= 0 -> uint max)
template<int CI, int STRIDE, int NB, int SOUT, int OUTMODE>
__global__ void __launch_bounds__(128)
conv_mma_kernel(const __half* __restrict__ in, const __half* __restrict__ Wp,
                const float* __restrict__ gamma, const float* __restrict__ beta,
                void* __restrict__ out, int Sin, int CO)
{
    using SM = ConvSm<STRIDE, NB, SOUT>;
    constexpr int NT = NB / 8;
    constexpr int HY = SM::HY, PX = SM::PX, HTOTP = SM::HTOTP;
    constexpr int TYO = SM::TYO;

    extern __shared__ __align__(16) char sm[];
    int* tbl = (int*)sm;
    char* sA = sm + SM::A_OFF;
    float* sT = (float*)sm;

    const int tid = threadIdx.x;
    const int w = tid >> 5, lane = tid & 31;
    const int g = lane >> 2, tg = lane & 3;

    const uint32_t uTile = (uint32_t)__cvta_generic_to_shared(sm + SM::TBLB);
    const uint32_t uA = (uint32_t)__cvta_generic_to_shared(sA);
    const uint32_t uB = (uint32_t)__cvta_generic_to_shared(sm + SM::B_OFF);
    const uint32_t aBase = uA + (uint32_t)((w * 32 + (lane & 15)) * 80 + (lane >> 4) * 16);
    const uint32_t bBase = uB + (uint32_t)((lane & 7) * 144 + (lane >> 3) * 16);

    const int nby = SOUT / TYO;
    const int bz = blockIdx.x / nby;
    const int by0 = (blockIdx.x % nby) * TYO;
    const int oc0 = blockIdx.y * NB;
    const int vbase = blockIdx.x * 128;

    const int y = tid / SOUT, x = tid % SOUT;
    const int oz = bz * STRIDE - 1, oy = by0 * STRIDE - 1;
    const size_t SinSq = (size_t)Sin * Sin;
    const size_t Sin3 = SinSq * Sin;
    const uint32_t* inu = (const uint32_t*)in;

    for (int idx = tid; idx < HTOTP; idx += 128) {
        int tz = idx / (HY * PX);
        int rem = idx - tz * (HY * PX);
        int ty = rem / PX;
        int px = rem - ty * PX;
        int gz = oz + tz, gy = oy + ty, gx0 = px * 2 - 2;
        int off = -1;
        if ((unsigned)gz < (unsigned)Sin && (unsigned)gy < (unsigned)Sin &&
            gx0 >= 0 && gx0 <= Sin - 2)
            off = (int)(((size_t)gz * SinSq + (size_t)gy * Sin + gx0) >> 1);
        tbl[idx] = off;
    }
    __syncthreads();

    float acc[2][NT][4];
#pragma unroll
    for (int mt = 0; mt < 2; mt++)
#pragma unroll
        for (int nt = 0; nt < NT; nt++)
#pragma unroll
            for (int q = 0; q < 4; q++) acc[mt][nt][q] = 0.f;

    {
        for (int idx = tid; idx < HTOTP; idx += 128) {
            int o = tbl[idx];
            cp4(uTile + idx * 4, inu + (o >= 0 ? o : 0), o >= 0 ? 4u : 0u);
        }
        const char* srcb = (const char*)(Wp + ((size_t)oc0) * 64);
        for (int u = tid; u < NB * 8; u += 128) {
            int co = u >> 3, seg = u & 7;
            cp16(uB + co * 144 + seg * 16, srcb + co * 128 + seg * 16);
        }
        cp_commit();
    }

    for (int ci = 0; ci < CI; ci++) {
        const int s = ci & 1;
        cp_wait0();
        __syncthreads();

        if (ci + 1 < CI) {
            const uint32_t* basep = inu + ((size_t)(ci + 1) * Sin3 >> 1);
            const uint32_t td = uTile + (s ^ 1) * SM::TILEB;
            for (int idx = tid; idx < HTOTP; idx += 128) {
                int o = tbl[idx];
                cp4(td + idx * 4, basep + (o >= 0 ? o : 0), o >= 0 ? 4u : 0u);
            }
            const char* srcb = (const char*)(Wp + ((size_t)(ci + 1) * CO + oc0) * 64);
            const uint32_t bd = uB + (s ^ 1) * (NB * 144);
            for (int u = tid; u < NB * 8; u += 128) {
                int co = u >> 3, seg = u & 7;
                cp16(bd + co * 144 + seg * 16, srcb + co * 128 + seg * 16);
            }
            cp_commit();
        }

        {
            const unsigned short* tp =
                (const unsigned short*)(sm + SM::TBLB + s * SM::TILEB);
            unsigned short t[27];
#pragma unroll
            for (int dz = 0; dz < 3; dz++)
#pragma unroll
                for (int dy = 0; dy < 3; dy++) {
                    const unsigned short* r =
                        tp + (dz * HY + y * STRIDE + dy) * (2 * PX) + x * STRIDE + 1;
                    t[(dz*3+dy)*3 + 0] = r[0];
                    t[(dz*3+dy)*3 + 1] = r[1];
                    t[(dz*3+dy)*3 + 2] = r[2];
                }
            uint32_t h2[16];
#pragma unroll
            for (int j = 0; j < 13; j++)
                h2[j] = (uint32_t)t[2*j] | ((uint32_t)t[2*j+1] << 16);
            h2[13] = (uint32_t)t[26];
            h2[14] = h2[15] = 0u;
            uint4* rowp = (uint4*)(sA + tid * 80);
            rowp[0] = make_uint4(h2[0], h2[1], h2[2], h2[3]);
            rowp[1] = make_uint4(h2[4], h2[5], h2[6], h2[7]);
            rowp[2] = make_uint4(h2[8], h2[9], h2[10], h2[11]);
            rowp[3] = make_uint4(h2[12], h2[13], h2[14], h2[15]);
        }
        __syncwarp();

        const uint32_t bS = bBase + s * (NB * 144);
        uint32_t ah[2][2][4];
#pragma unroll
        for (int mt = 0; mt < 2; mt++)
#pragma unroll
            for (int ks = 0; ks < 2; ks++)
                LDSM4(ah[mt][ks], aBase + mt * (16*80) + ks * 32);
#pragma unroll
        for (int nt = 0; nt < NT; nt++) {
            uint32_t bh[4], bl[4];
            LDSM4(bh, bS + nt * (8*144));
            LDSM4(bl, bS + nt * (8*144) + 64);
#pragma unroll
            for (int mt = 0; mt < 2; mt++) {
                MMA16816(acc[mt][nt], ah[mt][0], bh[0], bh[1]);
                MMA16816(acc[mt][nt], ah[mt][1], bh[2], bh[3]);
                MMA16816(acc[mt][nt], ah[mt][0], bl[0], bl[1]);
                MMA16816(acc[mt][nt], ah[mt][1], bl[2], bl[3]);
            }
        }
    }

    const float inv = rsqrtf(1.f + 1e-5f);
    const size_t S3 = (size_t)SOUT * SOUT * SOUT;
    const int v = vbase + tid;
    const int bevIdx0 = ((v >> 10) << 5) | (v & 31);   // z*32 + x (SOUT==32 for BEV layer)
#pragma unroll
    for (int half = 0; half < NB / 64; half++) {
        __syncthreads();
#pragma unroll
        for (int nt2 = 0; nt2 < 8; nt2++) {
            int nt = half * 8 + nt2;
#pragma unroll
            for (int mt = 0; mt < 2; mt++) {
                int vr0 = w * 32 + mt * 16 + g, vr1 = vr0 + 8;
                int co = nt2 * 8 + 2 * tg;
                sT[co * 132 + vr0]       = acc[mt][nt][0];
                sT[(co + 1) * 132 + vr0] = acc[mt][nt][1];
                sT[co * 132 + vr1]       = acc[mt][nt][2];
                sT[(co + 1) * 132 + vr1] = acc[mt][nt][3];
            }
        }
        __syncthreads();
        for (int co = 0; co < 64; co++) {
            int cog = oc0 + half * 64 + co;
            float sc = gamma[cog] * inv, bb = beta[cog];
            float val = fmaxf(sT[co * 132 + tid] * sc + bb, 0.f);
            if (OUTMODE == 1)
                atomicMax((unsigned int*)out + cog * 1024 + bevIdx0, __float_as_uint(val));
            else
                ((__half*)out)[(size_t)cog * S3 + vbase + tid] = __float2half_rn(val);
        }
    }
}

// ---------------------------------------------------------------- fp32 L1 (stride-1, CI=4) -> fp16 out
template<int CI, int TY, int TXT>
__global__ void __launch_bounds__(128, 4)
conv_s1_db_kernel(const float* __restrict__ in, const float* __restrict__ wgt,
                  const float* __restrict__ gamma, const float* __restrict__ beta,
                  __half* __restrict__ out, int Sin, int Sout)
{
    constexpr int TZ = 4, XPT = 8;
    constexpr int TXO = TXT * XPT;
    constexpr int HZ = TZ + 2, HY = TY + 2, HXO = TXO + 2;
    constexpr int HTOT = HZ * HY * HXO;
    constexpr int ITERS = (HTOT + 127) / 128;

    __shared__ int s_off[HTOT];
    __shared__ float s_in[2][HTOT];
    __shared__ __align__(16) float s_w[2][216];

    const int tid = threadIdx.x;
    const int lx = tid % TXT;
    const int ly = (tid / TXT) % TY;
    const int lz = tid / (TXT * TY);

    const int ntx = Sout / TXO, nty = Sout / TY;
    int bt = blockIdx.x;
    const int tx0 = (bt % ntx) * TXO; bt /= ntx;
    const int ty0 = (bt % nty) * TY;  bt /= nty;
    const int tz0 = bt * TZ;
    const int oc0 = blockIdx.y * 8;

    const int bz = tz0 - 1, by = ty0 - 1, bx = tx0 - 1;

    for (int idx = tid; idx < HTOT; idx += 128) {
        int iz = idx / (HY * HXO);
        int rem = idx - iz * (HY * HXO);
        int iy = rem / HXO;
        int ix = rem - iy * HXO;
        int gz = bz + iz, gy = by + iy, gx = bx + ix;
        int off = -1;
        if ((unsigned)gz < (unsigned)Sin && (unsigned)gy < (unsigned)Sin &&
            (unsigned)gx < (unsigned)Sin)
            off = (gz * Sin + gy) * Sin + gx;
        s_off[idx] = off;
    }

    const float* wp0 = nullptr; const float* wp1 = nullptr;
    {
        int t0 = tid >> 3, o0 = tid & 7;
        wp0 = wgt + ((size_t)(oc0 + o0) * CI) * 27 + t0;
        int i1 = tid + 128;
        if (i1 < 216) {
            int t1 = i1 >> 3, o1 = i1 & 7;
            wp1 = wgt + ((size_t)(oc0 + o1) * CI) * 27 + t1;
        }
    }
    __syncthreads();

    const size_t Sin3 = (size_t)Sin * Sin * Sin;
    unsigned sin_base = (unsigned)__cvta_generic_to_shared(&s_in[0][0]);
    unsigned sw_base  = (unsigned)__cvta_generic_to_shared(&s_w[0][0]);

    {
        const float* inc = in;
#pragma unroll
        for (int k = 0; k < ITERS; k++) {
            int idx = tid + k * 128;
            if (idx < HTOT) {
                int o = s_off[idx];
                cp4(sin_base + idx * 4, inc + (o >= 0 ? o : 0), o >= 0 ? 4u : 0u);
            }
        }
        cp4(sw_base + tid * 4, wp0, 4u);
        if (wp1) cp4(sw_base + (tid + 128) * 4, wp1, 4u);
        cp_commit();
    }

    ull acc[XPT][4];
#pragma unroll
    for (int i = 0; i < XPT; i++)
#pragma unroll
        for (int p = 0; p < 4; p++) acc[i][p] = 0ULL;

    const int iz0 = lz, iy0 = ly, ixb = lx * XPT;

    for (int ci = 0; ci < CI; ci++) {
        cp_wait0();
        __syncthreads();

        const int cur = ci & 1, nxt = cur ^ 1;
        if (ci + 1 < CI) {
            const float* inc = in + (size_t)(ci + 1) * Sin3;
            unsigned dstb = sin_base + nxt * (HTOT * 4);
#pragma unroll
            for (int k = 0; k < ITERS; k++) {
                int idx = tid + k * 128;
                if (idx < HTOT) {
                    int o = s_off[idx];
                    cp4(dstb + idx * 4, inc + (o >= 0 ? o : 0), o >= 0 ? 4u : 0u);
                }
            }
            unsigned dw = sw_base + nxt * (216 * 4);
            cp4(dw + tid * 4, wp0 + (ci + 1) * 27, 4u);
            if (wp1) cp4(dw + (tid + 128) * 4, wp1 + (ci + 1) * 27, 4u);
            cp_commit();
        } else {
            cp_commit();
        }

        const float* sbuf = &s_in[cur][0];
        const float* swb  = &s_w[cur][0];

#pragma unroll
        for (int dz = 0; dz < 3; dz++) {
#pragma unroll
            for (int dy = 0; dy < 3; dy++) {
                const float* row = &sbuf[((iz0 + dz) * HY + (iy0 + dy)) * HXO + ixb];
                ull vvp[10];
#pragma unroll
                for (int j = 0; j < 10; j++) { float r = row[j]; PACK2(vvp[j], r); }
#pragma unroll
                for (int dx = 0; dx < 3; dx++) {
                    const ull* wp = (const ull*)&swb[((dz * 3 + dy) * 3 + dx) * 8];
                    const ull w0 = wp[0], w1 = wp[1], w2 = wp[2], w3 = wp[3];
#pragma unroll
                    for (int xi = 0; xi < XPT; xi++) {
                        const ull vx = vvp[xi + dx];
                        FMA2(acc[xi][0], vx, w0, acc[xi][0]);
                        FMA2(acc[xi][1], vx, w1, acc[xi][1]);
                        FMA2(acc[xi][2], vx, w2, acc[xi][2]);
                        FMA2(acc[xi][3], vx, w3, acc[xi][3]);
                    }
                }
            }
        }
        __syncthreads();
    }

    const int oz = tz0 + lz, oy = ty0 + ly, ox0 = tx0 + lx * XPT;
    const float inv = rsqrtf(1.f + 1e-5f);
    const size_t S3 = (size_t)Sout * Sout * Sout;
    const size_t sp = ((size_t)oz * Sout + oy) * Sout + ox0;
#pragma unroll
    for (int p = 0; p < 4; p++) {
        const int ocA = oc0 + 2 * p, ocB = ocA + 1;
        const float sA = gamma[ocA] * inv, bA = beta[ocA];
        const float sB = gamma[ocB] * inv, bB = beta[ocB];
        float lo[XPT], hi[XPT];
#pragma unroll
        for (int xi = 0; xi < XPT; xi++) {
            UNPACK2(lo[xi], hi[xi], acc[xi][p]);
            lo[xi] = fmaxf(lo[xi] * sA + bA, 0.f);
            hi[xi] = fmaxf(hi[xi] * sB + bB, 0.f);
        }
        uint4 va, vb;
        va.x = packh2(lo[0], lo[1]); va.y = packh2(lo[2], lo[3]);
        va.z = packh2(lo[4], lo[5]); va.w = packh2(lo[6], lo[7]);
        vb.x = packh2(hi[0], hi[1]); vb.y = packh2(hi[2], hi[3]);
        vb.z = packh2(hi[4], hi[5]); vb.w = packh2(hi[6], hi[7]);
        *(uint4*)(out + (size_t)ocA * S3 + sp) = va;
        *(uint4*)(out + (size_t)ocB * S3 + sp) = vb;
    }
}

// ---------------------------------------------------------------- resize 32x32 -> 200x200
__global__ void resize_kernel(const float* __restrict__ bev, float* __restrict__ out) {
    int i = blockIdx.x * blockDim.x + threadIdx.x;
    if (i >= 256 * 200 * 200) return;
    int ox = i % 200;
    int t  = i / 200;
    int oy = t % 200;
    int c  = t / 200;
    const float scale = 32.f / 200.f;
    float sy = (oy + 0.5f) * scale - 0.5f;
    float sx = (ox + 0.5f) * scale - 0.5f;
    int y0f = (int)floorf(sy); float fy = sy - (float)y0f;
    int x0f = (int)floorf(sx); float fx = sx - (float)x0f;
    int y0 = min(max(y0f, 0), 31), y1 = min(max(y0f + 1, 0), 31);
    int x0 = min(max(x0f, 0), 31), x1 = min(max(x0f + 1, 0), 31);
    const float* b = bev + (size_t)c * 1024;
    float v00 = b[y0 * 32 + x0], v01 = b[y0 * 32 + x1];
    float v10 = b[y1 * 32 + x0], v11 = b[y1 * 32 + x1];
    float v0 = v00 + (v01 - v00) * fx;
    float v1 = v10 + (v11 - v10) * fx;
    out[i] = v0 + (v1 - v0) * fy;
}

// ---------------------------------------------------------------- launch
extern "C" void kernel_launch(void* const* d_in, const int* in_sizes, int n_in,
                              void* d_out, int out_size) {
    const float* points = (const float*)d_in[0];
    const float* w[6]; const float* gm[6]; const float* bt[6];

    if (n_in >= 4 && in_sizes[2] == in_sizes[3] && in_sizes[2] <= 1024) {
        for (int i = 0; i < 6; i++) {
            w[i]  = (const float*)d_in[1 + 3*i];
            gm[i] = (const float*)d_in[2 + 3*i];
            bt[i] = (const float*)d_in[3 + 3*i];
        }
    } else {
        for (int i = 0; i < 6; i++) {
            w[i]  = (const float*)d_in[1 + i];
            gm[i] = (const float*)d_in[7 + i];
            bt[i] = (const float*)d_in[13 + i];
        }
    }
    const int N = in_sizes[0] / 4;

    float *A, *B; __half* W;
    cudaGetSymbolAddress((void**)&A, g_bufA);
    cudaGetSymbolAddress((void**)&B, g_bufB);
    cudaGetSymbolAddress((void**)&W, g_bufW);
    __half* Ah = (__half*)A;
    __half* Bh = (__half*)B;

    const int SM_L2 = ConvSm<2,  64, 64>::TOTAL;
    const int SM_L3 = ConvSm<1,  64, 64>::TOTAL;
    const int SM_L4 = ConvSm<2, 128, 32>::TOTAL;
    const int SM_L5 = ConvSm<1, 128, 32>::TOTAL;
    static bool attr_done = false;
    if (!attr_done) {
        cudaFuncSetAttribute(conv_mma_kernel< 32, 2,  64, 64, 0>, cudaFuncAttributeMaxDynamicSharedMemorySize, SM_L2);
        cudaFuncSetAttribute(conv_mma_kernel< 64, 1,  64, 64, 0>, cudaFuncAttributeMaxDynamicSharedMemorySize, SM_L3);
        cudaFuncSetAttribute(conv_mma_kernel< 64, 2, 128, 32, 0>, cudaFuncAttributeMaxDynamicSharedMemorySize, SM_L4);
        cudaFuncSetAttribute(conv_mma_kernel<128, 1, 128, 32, 0>, cudaFuncAttributeMaxDynamicSharedMemorySize, SM_L5);
        cudaFuncSetAttribute(conv_mma_kernel<128, 1, 128, 32, 1>, cudaFuncAttributeMaxDynamicSharedMemorySize, SM_L5);
        attr_done = true;
    }

    // fused weight prep (hi/lo fp16 split)
    prep_all_kernel<<<496, 128>>>(w[1], w[2], w[3], w[4], w[5], W);
    __half* W2 = W;
    __half* W3 = W + 131072;
    __half* W4 = W + 393216;
    __half* W5 = W + 917504;
    __half* W6 = W + 1966080;

    // 1. voxelize into A (4,128^3) fp32
    const int gridElems = 4 * G3;
    zero_kernel<<<(gridElems + 255) / 256, 256>>>(A, gridElems);
    voxelize_kernel<<<(N + 255) / 256, 256>>>((const float4*)points, A, N);

    // 2. conv stack (fp16 activations between layers)
    // L1 fp32 in -> fp16 out: 4->32 s1 @128^3, A -> B
    { dim3 gr(2 * 32 * 32, 4); conv_s1_db_kernel<4, 4, 8><<<gr, 128>>>(A, w[0], gm[0], bt[0], Bh, 128, 128); }
    // L2: 32->64 s2 -> 64^3, B -> A
    { dim3 gr(2048, 1); conv_mma_kernel< 32, 2,  64, 64, 0><<<gr, 128, SM_L2>>>(Bh, W2, gm[1], bt[1], Ah, 128,  64); }
    // L3: 64->64 s1 @64^3, A -> B
    { dim3 gr(2048, 1); conv_mma_kernel< 64, 1,  64, 64, 0><<<gr, 128, SM_L3>>>(Ah, W3, gm[2], bt[2], Bh,  64,  64); }
    // L4: 64->128 s2 -> 32^3, B -> A
    { dim3 gr( 256, 1); conv_mma_kernel< 64, 2, 128, 32, 0><<<gr, 128, SM_L4>>>(Bh, W4, gm[3], bt[3], Ah,  64, 128); }
    // L5: 128->128 s1 @32^3, A -> B
    { dim3 gr( 256, 1); conv_mma_kernel<128, 1, 128, 32, 0><<<gr, 128, SM_L5>>>(Ah, W5, gm[4], bt[4], Bh,  32, 128); }
    // 3. zero BEV accumulator (256x32x32 fp32 in A; values >= 0 so 0 is the max-identity)
    zero_kernel<<<(256 * 1024 + 255) / 256, 256>>>(A, 256 * 1024);
    // L6 + fused bevmax: 128->256 s1 @32^3, B -> atomicMax into A
    { dim3 gr( 256, 2); conv_mma_kernel<128, 1, 128, 32, 1><<<gr, 128, SM_L5>>>(Bh, W6, gm[5], bt[5], A,  32, 256); }

    // 4. bilinear resize to (256,200,200)
    resize_kernel<<<(256 * 200 * 200 + 255) / 256, 256>>>(A, (float*)d_out);
}

// round 17
// speedup vs baseline: 2.3277x; 1.3708x over previous
#include <cuda_runtime.h>
#include <cuda_fp16.h>
#include <math.h>
#include <stdint.h>

#define G 128
#define G3 (G*G*G)

typedef unsigned long long ull;

// ---------------- packed f32x2 helpers (fp32 L1 kernel) ----------------
#define FMA2(d, a, b, c) \
    asm("fma.rn.f32x2 %0, %1, %2, %3;" : "=l"(d) : "l"(a), "l"(b), "l"(c))
#define PACK2(d, x) \
    asm("mov.b64 %0, {%1, %2};" : "=l"(d) : "r"(__float_as_uint(x)), "r"(__float_as_uint(x)))
#define UNPACK2(lo, hi, v) \
    asm("mov.b64 {%0, %1}, %2;" : "=f"(lo), "=f"(hi) : "l"(v))

__device__ __forceinline__ void cp4(unsigned dst, const void* src, unsigned sz) {
    asm volatile("cp.async.ca.shared.global [%0], [%1], 4, %2;" :: "r"(dst), "l"(src), "r"(sz));
}
__device__ __forceinline__ void cp16(unsigned dst, const void* src) {
    asm volatile("cp.async.cg.shared.global [%0], [%1], 16;" :: "r"(dst), "l"(src));
}
__device__ __forceinline__ void cp_commit() { asm volatile("cp.async.commit_group;"); }
__device__ __forceinline__ void cp_wait0() { asm volatile("cp.async.wait_group 0;"); }

// m16n8k16 fp16 MMA, f32 accumulate
#define MMA16816(d, a, b0v, b1v) \
    asm volatile("mma.sync.aligned.m16n8k16.row.col.f32.f16.f16.f32 " \
        "{%0,%1,%2,%3}, {%4,%5,%6,%7}, {%8,%9}, {%0,%1,%2,%3};" \
        : "+f"((d)[0]), "+f"((d)[1]), "+f"((d)[2]), "+f"((d)[3]) \
        : "r"((a)[0]), "r"((a)[1]), "r"((a)[2]), "r"((a)[3]), \
          "r"(b0v), "r"(b1v))

#define LDSM4(r, addr) \
    asm volatile("ldmatrix.sync.aligned.m8n8.x4.shared.b16 {%0,%1,%2,%3}, [%4];" \
        : "=r"((r)[0]), "=r"((r)[1]), "=r"((r)[2]), "=r"((r)[3]) : "r"(addr))

__device__ __forceinline__ uint32_t packh2(float a, float b) {
    __half2 h = __floats2half2_rn(a, b);
    return *(uint32_t*)&h;
}

// ---------------- scratch buffers ----------------
__device__ float g_bufA[16777216];     // 67MB
__device__ float g_bufB[67108864];     // 268MB
__device__ __half g_bufW[4063232];     // split fp16 weights

// ---------------------------------------------------------------- utilities
__global__ void zero_kernel(float* __restrict__ p, int n) {
    int i = blockIdx.x * blockDim.x + threadIdx.x;
    if (i < n) p[i] = 0.f;
}

// ---------------------------------------------------------------- voxelize
__global__ void voxelize_kernel(const float4* __restrict__ pts, float* __restrict__ grid, int N) {
    int i = blockIdx.x * blockDim.x + threadIdx.x;
    if (i >= N) return;
    float4 p = pts[i];
    if (p.x < -32.f || p.x > 32.f ||
        p.y < -32.f || p.y > 32.f ||
        p.z < -32.f || p.z > 32.f) return;
    int cx = (int)floorf((p.x + 32.f) * 2.f);
    int cy = (int)floorf((p.y + 32.f) * 2.f);
    int cz = (int)floorf((p.z + 32.f) * 2.f);
    cx = cx < 0 ? 0 : (cx > G-1 ? G-1 : cx);
    cy = cy < 0 ? 0 : (cy > G-1 ? G-1 : cy);
    cz = cz < 0 ? 0 : (cz > G-1 ? G-1 : cz);
    int base = (cz * G + cy) * G + cx;
    atomicAdd(&grid[0*G3 + base], p.x);
    atomicAdd(&grid[1*G3 + base], p.y);
    atomicAdd(&grid[2*G3 + base], p.z);
    atomicAdd(&grid[3*G3 + base], p.w);
}

// ---------------------------------------------------------------- fused weight prep (hi/lo fp16)
__global__ void prep_all_kernel(const float* __restrict__ w2, const float* __restrict__ w3,
                                const float* __restrict__ w4, const float* __restrict__ w5,
                                const float* __restrict__ w6, __half* __restrict__ dst) {
    int idx = blockIdx.x * blockDim.x + threadIdx.x;
    const float* w; int CO, CI; size_t off;
    if (idx < 2048)                  { w = w2; CO =  64; CI =  32; off = 0; }
    else if ((idx -= 2048) < 4096)   { w = w3; CO =  64; CI =  64; off = 131072; }
    else if ((idx -= 4096) < 8192)   { w = w4; CO = 128; CI =  64; off = 393216; }
    else if ((idx -= 8192) < 16384)  { w = w5; CO = 128; CI = 128; off = 917504; }
    else if ((idx -= 16384) < 32768) { w = w6; CO = 256; CI = 128; off = 1966080; }
    else return;
    int ci = idx / CO, co = idx - ci * CO;
    const float* ws = w + ((size_t)co * CI + ci) * 27;

    uint32_t h2[16], l2[16];
#pragma unroll
    for (int p = 0; p < 13; p++) {
        float a = ws[2*p], b = ws[2*p+1];
        __half2 h = __floats2half2_rn(a, b);
        float2 hf = __half22float2(h);
        h2[p] = *(uint32_t*)&h;
        l2[p] = packh2(a - hf.x, b - hf.y);
    }
    {
        float a = ws[26];
        __half ha = __float2half_rn(a);
        __half2 h = __halves2half2(ha, __ushort_as_half(0));
        h2[13] = *(uint32_t*)&h;
        l2[13] = packh2(a - __half2float(ha), 0.f);
        h2[14] = h2[15] = l2[14] = l2[15] = 0u;
    }
    uint4* o = (uint4*)(dst + off + (size_t)(ci * CO + co) * 64);
    o[0] = make_uint4(h2[0], h2[1], h2[2], h2[3]);
    o[1] = make_uint4(h2[4], h2[5], h2[6], h2[7]);
    o[2] = make_uint4(h2[8], h2[9], h2[10], h2[11]);
    o[3] = make_uint4(h2[12], h2[13], h2[14], h2[15]);
    o[4] = make_uint4(l2[0], l2[1], l2[2], l2[3]);
    o[5] = make_uint4(l2[4], l2[5], l2[6], l2[7]);
    o[6] = make_uint4(l2[8], l2[9], l2[10], l2[11]);
    o[7] = make_uint4(l2[12], l2[13], l2[14], l2[15]);
}

// ---------------------------------------------------------------- smem size helpers
__host__ __device__ constexpr int align16(int x) { return (x + 15) & ~15; }
__host__ __device__ constexpr int cmax(int a, int b) { return a > b ? a : b; }

template<int STRIDE, int NB, int SOUT>
struct ConvSm {
    static constexpr int TYO  = 128 / SOUT;
    static constexpr int HX   = (SOUT - 1) * STRIDE + 3;
    static constexpr int HY   = (TYO - 1) * STRIDE + 3;
    static constexpr int PX   = (HX + 2) / 2;
    static constexpr int HTOTP = 3 * HY * PX;
    static constexpr int TBLB = align16(HTOTP * 4);
    static constexpr int TILEB = align16(HTOTP * 4);
    static constexpr int A_OFF = TBLB + 2 * TILEB;
    static constexpr int B_OFF = A_OFF + 128 * 80;
    static constexpr int TOTAL = cmax(B_OFF + 2 * NB * 80, 64 * 132 * 4);
};

// ---------------------------------------------------------------- mma implicit-GEMM conv
// A: fp16 activations; B: fp16 weights (hi only) -> 1 product.
// OUTMODE: 0 = fp16 store, 1 = fused BEV atomicMax (post-ReLU >= 0 -> uint max)
template<int CI, int STRIDE, int NB, int SOUT, int OUTMODE>
__global__ void __launch_bounds__(128)
conv_mma_kernel(const __half* __restrict__ in, const __half* __restrict__ Wp,
                const float* __restrict__ gamma, const float* __restrict__ beta,
                void* __restrict__ out, int Sin, int CO)
{
    using SM = ConvSm<STRIDE, NB, SOUT>;
    constexpr int NT = NB / 8;
    constexpr int HY = SM::HY, PX = SM::PX, HTOTP = SM::HTOTP;
    constexpr int TYO = SM::TYO;

    extern __shared__ __align__(16) char sm[];
    int* tbl = (int*)sm;
    char* sA = sm + SM::A_OFF;
    float* sT = (float*)sm;

    const int tid = threadIdx.x;
    const int w = tid >> 5, lane = tid & 31;
    const int g = lane >> 2, tg = lane & 3;

    const uint32_t uTile = (uint32_t)__cvta_generic_to_shared(sm + SM::TBLB);
    const uint32_t uA = (uint32_t)__cvta_generic_to_shared(sA);
    const uint32_t uB = (uint32_t)__cvta_generic_to_shared(sm + SM::B_OFF);
    const uint32_t aBase = uA + (uint32_t)((w * 32 + (lane & 15)) * 80 + (lane >> 4) * 16);
    const uint32_t bBase = uB + (uint32_t)((lane & 7) * 80 + (lane >> 3) * 16);

    const int nby = SOUT / TYO;
    const int bz = blockIdx.x / nby;
    const int by0 = (blockIdx.x % nby) * TYO;
    const int oc0 = blockIdx.y * NB;
    const int vbase = blockIdx.x * 128;

    const int y = tid / SOUT, x = tid % SOUT;
    const int oz = bz * STRIDE - 1, oy = by0 * STRIDE - 1;
    const size_t SinSq = (size_t)Sin * Sin;
    const size_t Sin3 = SinSq * Sin;
    const uint32_t* inu = (const uint32_t*)in;

    for (int idx = tid; idx < HTOTP; idx += 128) {
        int tz = idx / (HY * PX);
        int rem = idx - tz * (HY * PX);
        int ty = rem / PX;
        int px = rem - ty * PX;
        int gz = oz + tz, gy = oy + ty, gx0 = px * 2 - 2;
        int off = -1;
        if ((unsigned)gz < (unsigned)Sin && (unsigned)gy < (unsigned)Sin &&
            gx0 >= 0 && gx0 <= Sin - 2)
            off = (int)(((size_t)gz * SinSq + (size_t)gy * Sin + gx0) >> 1);
        tbl[idx] = off;
    }
    __syncthreads();

    float acc[2][NT][4];
#pragma unroll
    for (int mt = 0; mt < 2; mt++)
#pragma unroll
        for (int nt = 0; nt < NT; nt++)
#pragma unroll
            for (int q = 0; q < 4; q++) acc[mt][nt][q] = 0.f;

    {
        for (int idx = tid; idx < HTOTP; idx += 128) {
            int o = tbl[idx];
            cp4(uTile + idx * 4, inu + (o >= 0 ? o : 0), o >= 0 ? 4u : 0u);
        }
        const char* srcb = (const char*)(Wp + ((size_t)oc0) * 64);
        for (int u = tid; u < NB * 4; u += 128) {
            int co = u >> 2, seg = u & 3;
            cp16(uB + co * 80 + seg * 16, srcb + co * 128 + seg * 16);
        }
        cp_commit();
    }

    for (int ci = 0; ci < CI; ci++) {
        const int s = ci & 1;
        cp_wait0();
        __syncthreads();

        if (ci + 1 < CI) {
            const uint32_t* basep = inu + ((size_t)(ci + 1) * Sin3 >> 1);
            const uint32_t td = uTile + (s ^ 1) * SM::TILEB;
            for (int idx = tid; idx < HTOTP; idx += 128) {
                int o = tbl[idx];
                cp4(td + idx * 4, basep + (o >= 0 ? o : 0), o >= 0 ? 4u : 0u);
            }
            const char* srcb = (const char*)(Wp + ((size_t)(ci + 1) * CO + oc0) * 64);
            const uint32_t bd = uB + (s ^ 1) * (NB * 80);
            for (int u = tid; u < NB * 4; u += 128) {
                int co = u >> 2, seg = u & 3;
                cp16(bd + co * 80 + seg * 16, srcb + co * 128 + seg * 16);
            }
            cp_commit();
        }

        {
            const unsigned short* tp =
                (const unsigned short*)(sm + SM::TBLB + s * SM::TILEB);
            unsigned short t[27];
#pragma unroll
            for (int dz = 0; dz < 3; dz++)
#pragma unroll
                for (int dy = 0; dy < 3; dy++) {
                    const unsigned short* r =
                        tp + (dz * HY + y * STRIDE + dy) * (2 * PX) + x * STRIDE + 1;
                    t[(dz*3+dy)*3 + 0] = r[0];
                    t[(dz*3+dy)*3 + 1] = r[1];
                    t[(dz*3+dy)*3 + 2] = r[2];
                }
            uint32_t h2[16];
#pragma unroll
            for (int j = 0; j < 13; j++)
                h2[j] = (uint32_t)t[2*j] | ((uint32_t)t[2*j+1] << 16);
            h2[13] = (uint32_t)t[26];
            h2[14] = h2[15] = 0u;
            uint4* rowp = (uint4*)(sA + tid * 80);
            rowp[0] = make_uint4(h2[0], h2[1], h2[2], h2[3]);
            rowp[1] = make_uint4(h2[4], h2[5], h2[6], h2[7]);
            rowp[2] = make_uint4(h2[8], h2[9], h2[10], h2[11]);
            rowp[3] = make_uint4(h2[12], h2[13], h2[14], h2[15]);
        }
        __syncwarp();

        const uint32_t bS = bBase + s * (NB * 80);
        uint32_t ah[2][2][4];
#pragma unroll
        for (int mt = 0; mt < 2; mt++)
#pragma unroll
            for (int ks = 0; ks < 2; ks++)
                LDSM4(ah[mt][ks], aBase + mt * (16*80) + ks * 32);
#pragma unroll
        for (int nt = 0; nt < NT; nt++) {
            uint32_t bh[4];
            LDSM4(bh, bS + nt * (8*80));
#pragma unroll
            for (int mt = 0; mt < 2; mt++) {
                MMA16816(acc[mt][nt], ah[mt][0], bh[0], bh[1]);
                MMA16816(acc[mt][nt], ah[mt][1], bh[2], bh[3]);
            }
        }
    }

    const float inv = rsqrtf(1.f + 1e-5f);
    const size_t S3 = (size_t)SOUT * SOUT * SOUT;
    const int v = vbase + tid;
    const int bevIdx0 = ((v >> 10) << 5) | (v & 31);   // z*32 + x (SOUT==32 for BEV layer)
#pragma unroll
    for (int half = 0; half < NB / 64; half++) {
        __syncthreads();
#pragma unroll
        for (int nt2 = 0; nt2 < 8; nt2++) {
            int nt = half * 8 + nt2;
#pragma unroll
            for (int mt = 0; mt < 2; mt++) {
                int vr0 = w * 32 + mt * 16 + g, vr1 = vr0 + 8;
                int co = nt2 * 8 + 2 * tg;
                sT[co * 132 + vr0]       = acc[mt][nt][0];
                sT[(co + 1) * 132 + vr0] = acc[mt][nt][1];
                sT[co * 132 + vr1]       = acc[mt][nt][2];
                sT[(co + 1) * 132 + vr1] = acc[mt][nt][3];
            }
        }
        __syncthreads();
        for (int co = 0; co < 64; co++) {
            int cog = oc0 + half * 64 + co;
            float sc = gamma[cog] * inv, bb = beta[cog];
            float val = fmaxf(sT[co * 132 + tid] * sc + bb, 0.f);
            if (OUTMODE == 1)
                atomicMax((unsigned int*)out + cog * 1024 + bevIdx0, __float_as_uint(val));
            else
                ((__half*)out)[(size_t)cog * S3 + vbase + tid] = __float2half_rn(val);
        }
    }
}

// ---------------------------------------------------------------- fp32 L1 (stride-1, CI=4) -> fp16 out
template<int CI, int TY, int TXT>
__global__ void __launch_bounds__(128, 4)
conv_s1_db_kernel(const float* __restrict__ in, const float* __restrict__ wgt,
                  const float* __restrict__ gamma, const float* __restrict__ beta,
                  __half* __restrict__ out, int Sin, int Sout)
{
    constexpr int TZ = 4, XPT = 8;
    constexpr int TXO = TXT * XPT;
    constexpr int HZ = TZ + 2, HY = TY + 2, HXO = TXO + 2;
    constexpr int HTOT = HZ * HY * HXO;
    constexpr int ITERS = (HTOT + 127) / 128;

    __shared__ int s_off[HTOT];
    __shared__ float s_in[2][HTOT];
    __shared__ __align__(16) float s_w[2][216];

    const int tid = threadIdx.x;
    const int lx = tid % TXT;
    const int ly = (tid / TXT) % TY;
    const int lz = tid / (TXT * TY);

    const int ntx = Sout / TXO, nty = Sout / TY;
    int bt = blockIdx.x;
    const int tx0 = (bt % ntx) * TXO; bt /= ntx;
    const int ty0 = (bt % nty) * TY;  bt /= nty;
    const int tz0 = bt * TZ;
    const int oc0 = blockIdx.y * 8;

    const int bz = tz0 - 1, by = ty0 - 1, bx = tx0 - 1;

    for (int idx = tid; idx < HTOT; idx += 128) {
        int iz = idx / (HY * HXO);
        int rem = idx - iz * (HY * HXO);
        int iy = rem / HXO;
        int ix = rem - iy * HXO;
        int gz = bz + iz, gy = by + iy, gx = bx + ix;
        int off = -1;
        if ((unsigned)gz < (unsigned)Sin && (unsigned)gy < (unsigned)Sin &&
            (unsigned)gx < (unsigned)Sin)
            off = (gz * Sin + gy) * Sin + gx;
        s_off[idx] = off;
    }

    const float* wp0 = nullptr; const float* wp1 = nullptr;
    {
        int t0 = tid >> 3, o0 = tid & 7;
        wp0 = wgt + ((size_t)(oc0 + o0) * CI) * 27 + t0;
        int i1 = tid + 128;
        if (i1 < 216) {
            int t1 = i1 >> 3, o1 = i1 & 7;
            wp1 = wgt + ((size_t)(oc0 + o1) * CI) * 27 + t1;
        }
    }
    __syncthreads();

    const size_t Sin3 = (size_t)Sin * Sin * Sin;
    unsigned sin_base = (unsigned)__cvta_generic_to_shared(&s_in[0][0]);
    unsigned sw_base  = (unsigned)__cvta_generic_to_shared(&s_w[0][0]);

    {
        const float* inc = in;
#pragma unroll
        for (int k = 0; k < ITERS; k++) {
            int idx = tid + k * 128;
            if (idx < HTOT) {
                int o = s_off[idx];
                cp4(sin_base + idx * 4, inc + (o >= 0 ? o : 0), o >= 0 ? 4u : 0u);
            }
        }
        cp4(sw_base + tid * 4, wp0, 4u);
        if (wp1) cp4(sw_base + (tid + 128) * 4, wp1, 4u);
        cp_commit();
    }

    ull acc[XPT][4];
#pragma unroll
    for (int i = 0; i < XPT; i++)
#pragma unroll
        for (int p = 0; p < 4; p++) acc[i][p] = 0ULL;

    const int iz0 = lz, iy0 = ly, ixb = lx * XPT;

    for (int ci = 0; ci < CI; ci++) {
        cp_wait0();
        __syncthreads();

        const int cur = ci & 1, nxt = cur ^ 1;
        if (ci + 1 < CI) {
            const float* inc = in + (size_t)(ci + 1) * Sin3;
            unsigned dstb = sin_base + nxt * (HTOT * 4);
#pragma unroll
            for (int k = 0; k < ITERS; k++) {
                int idx = tid + k * 128;
                if (idx < HTOT) {
                    int o = s_off[idx];
                    cp4(dstb + idx * 4, inc + (o >= 0 ? o : 0), o >= 0 ? 4u : 0u);
                }
            }
            unsigned dw = sw_base + nxt * (216 * 4);
            cp4(dw + tid * 4, wp0 + (ci + 1) * 27, 4u);
            if (wp1) cp4(dw + (tid + 128) * 4, wp1 + (ci + 1) * 27, 4u);
            cp_commit();
        } else {
            cp_commit();
        }

        const float* sbuf = &s_in[cur][0];
        const float* swb  = &s_w[cur][0];

#pragma unroll
        for (int dz = 0; dz < 3; dz++) {
#pragma unroll
            for (int dy = 0; dy < 3; dy++) {
                const float* row = &sbuf[((iz0 + dz) * HY + (iy0 + dy)) * HXO + ixb];
                ull vvp[10];
#pragma unroll
                for (int j = 0; j < 10; j++) { float r = row[j]; PACK2(vvp[j], r); }
#pragma unroll
                for (int dx = 0; dx < 3; dx++) {
                    const ull* wp = (const ull*)&swb[((dz * 3 + dy) * 3 + dx) * 8];
                    const ull w0 = wp[0], w1 = wp[1], w2 = wp[2], w3 = wp[3];
#pragma unroll
                    for (int xi = 0; xi < XPT; xi++) {
                        const ull vx = vvp[xi + dx];
                        FMA2(acc[xi][0], vx, w0, acc[xi][0]);
                        FMA2(acc[xi][1], vx, w1, acc[xi][1]);
                        FMA2(acc[xi][2], vx, w2, acc[xi][2]);
                        FMA2(acc[xi][3], vx, w3, acc[xi][3]);
                    }
                }
            }
        }
        __syncthreads();
    }

    const int oz = tz0 + lz, oy = ty0 + ly, ox0 = tx0 + lx * XPT;
    const float inv = rsqrtf(1.f + 1e-5f);
    const size_t S3 = (size_t)Sout * Sout * Sout;
    const size_t sp = ((size_t)oz * Sout + oy) * Sout + ox0;
#pragma unroll
    for (int p = 0; p < 4; p++) {
        const int ocA = oc0 + 2 * p, ocB = ocA + 1;
        const float sA = gamma[ocA] * inv, bA = beta[ocA];
        const float sB = gamma[ocB] * inv, bB = beta[ocB];
        float lo[XPT], hi[XPT];
#pragma unroll
        for (int xi = 0; xi < XPT; xi++) {
            UNPACK2(lo[xi], hi[xi], acc[xi][p]);
            lo[xi] = fmaxf(lo[xi] * sA + bA, 0.f);
            hi[xi] = fmaxf(hi[xi] * sB + bB, 0.f);
        }
        uint4 va, vb;
        va.x = packh2(lo[0], lo[1]); va.y = packh2(lo[2], lo[3]);
        va.z = packh2(lo[4], lo[5]); va.w = packh2(lo[6], lo[7]);
        vb.x = packh2(hi[0], hi[1]); vb.y = packh2(hi[2], hi[3]);
        vb.z = packh2(hi[4], hi[5]); vb.w = packh2(hi[6], hi[7]);
        *(uint4*)(out + (size_t)ocA * S3 + sp) = va;
        *(uint4*)(out + (size_t)ocB * S3 + sp) = vb;
    }
}

// ---------------------------------------------------------------- resize 32x32 -> 200x200
__global__ void resize_kernel(const float* __restrict__ bev, float* __restrict__ out) {
    int i = blockIdx.x * blockDim.x + threadIdx.x;
    if (i >= 256 * 200 * 200) return;
    int ox = i % 200;
    int t  = i / 200;
    int oy = t % 200;
    int c  = t / 200;
    const float scale = 32.f / 200.f;
    float sy = (oy + 0.5f) * scale - 0.5f;
    float sx = (ox + 0.5f) * scale - 0.5f;
    int y0f = (int)floorf(sy); float fy = sy - (float)y0f;
    int x0f = (int)floorf(sx); float fx = sx - (float)x0f;
    int y0 = min(max(y0f, 0), 31), y1 = min(max(y0f + 1, 0), 31);
    int x0 = min(max(x0f, 0), 31), x1 = min(max(x0f + 1, 0), 31);
    const float* b = bev + (size_t)c * 1024;
    float v00 = b[y0 * 32 + x0], v01 = b[y0 * 32 + x1];
    float v10 = b[y1 * 32 + x0], v11 = b[y1 * 32 + x1];
    float v0 = v00 + (v01 - v00) * fx;
    float v1 = v10 + (v11 - v10) * fx;
    out[i] = v0 + (v1 - v0) * fy;
}

// ---------------------------------------------------------------- launch
extern "C" void kernel_launch(void* const* d_in, const int* in_sizes, int n_in,
                              void* d_out, int out_size) {
    const float* points = (const float*)d_in[0];
    const float* w[6]; const float* gm[6]; const float* bt[6];

    if (n_in >= 4 && in_sizes[2] == in_sizes[3] && in_sizes[2] <= 1024) {
        for (int i = 0; i < 6; i++) {
            w[i]  = (const float*)d_in[1 + 3*i];
            gm[i] = (const float*)d_in[2 + 3*i];
            bt[i] = (const float*)d_in[3 + 3*i];
        }
    } else {
        for (int i = 0; i < 6; i++) {
            w[i]  = (const float*)d_in[1 + i];
            gm[i] = (const float*)d_in[7 + i];
            bt[i] = (const float*)d_in[13 + i];
        }
    }
    const int N = in_sizes[0] / 4;

    float *A, *B; __half* W;
    cudaGetSymbolAddress((void**)&A, g_bufA);
    cudaGetSymbolAddress((void**)&B, g_bufB);
    cudaGetSymbolAddress((void**)&W, g_bufW);
    __half* Ah = (__half*)A;
    __half* Bh = (__half*)B;

    const int SM_L2 = ConvSm<2,  64, 64>::TOTAL;
    const int SM_L3 = ConvSm<1,  64, 64>::TOTAL;
    const int SM_L4 = ConvSm<2, 128, 32>::TOTAL;
    const int SM_L5 = ConvSm<1, 128, 32>::TOTAL;
    static bool attr_done = false;
    if (!attr_done) {
        cudaFuncSetAttribute(conv_mma_kernel< 32, 2,  64, 64, 0>, cudaFuncAttributeMaxDynamicSharedMemorySize, SM_L2);
        cudaFuncSetAttribute(conv_mma_kernel< 64, 1,  64, 64, 0>, cudaFuncAttributeMaxDynamicSharedMemorySize, SM_L3);
        cudaFuncSetAttribute(conv_mma_kernel< 64, 2, 128, 32, 0>, cudaFuncAttributeMaxDynamicSharedMemorySize, SM_L4);
        cudaFuncSetAttribute(conv_mma_kernel<128, 1, 128, 32, 0>, cudaFuncAttributeMaxDynamicSharedMemorySize, SM_L5);
        cudaFuncSetAttribute(conv_mma_kernel<128, 1, 128, 32, 1>, cudaFuncAttributeMaxDynamicSharedMemorySize, SM_L5);
        attr_done = true;
    }

    // fused weight prep (hi/lo fp16 split; only hi rows consumed by the 1-product path)
    prep_all_kernel<<<496, 128>>>(w[1], w[2], w[3], w[4], w[5], W);
    __half* W2 = W;
    __half* W3 = W + 131072;
    __half* W4 = W + 393216;
    __half* W5 = W + 917504;
    __half* W6 = W + 1966080;

    // 1. voxelize into A (4,128^3) fp32
    const int gridElems = 4 * G3;
    zero_kernel<<<(gridElems + 255) / 256, 256>>>(A, gridElems);
    voxelize_kernel<<<(N + 255) / 256, 256>>>((const float4*)points, A, N);

    // 2. conv stack (fp16 activations between layers)
    // L1 fp32 in -> fp16 out: 4->32 s1 @128^3, A -> B
    { dim3 gr(2 * 32 * 32, 4); conv_s1_db_kernel<4, 4, 8><<<gr, 128>>>(A, w[0], gm[0], bt[0], Bh, 128, 128); }
    // L2: 32->64 s2 -> 64^3, B -> A
    { dim3 gr(2048, 1); conv_mma_kernel< 32, 2,  64, 64, 0><<<gr, 128, SM_L2>>>(Bh, W2, gm[1], bt[1], Ah, 128,  64); }
    // L3: 64->64 s1 @64^3, A -> B
    { dim3 gr(2048, 1); conv_mma_kernel< 64, 1,  64, 64, 0><<<gr, 128, SM_L3>>>(Ah, W3, gm[2], bt[2], Bh,  64,  64); }
    // L4: 64->128 s2 -> 32^3, B -> A
    { dim3 gr( 256, 1); conv_mma_kernel< 64, 2, 128, 32, 0><<<gr, 128, SM_L4>>>(Bh, W4, gm[3], bt[3], Ah,  64, 128); }
    // L5: 128->128 s1 @32^3, A -> B
    { dim3 gr( 256, 1); conv_mma_kernel<128, 1, 128, 32, 0><<<gr, 128, SM_L5>>>(Ah, W5, gm[4], bt[4], Bh,  32, 128); }
    // 3. zero BEV accumulator (256x32x32 fp32 in A)
    zero_kernel<<<(256 * 1024 + 255) / 256, 256>>>(A, 256 * 1024);
    // L6 + fused bevmax: 128->256 s1 @32^3, B -> atomicMax into A
    { dim3 gr( 256, 2); conv_mma_kernel<128, 1, 128, 32, 1><<<gr, 128, SM_L5>>>(Bh, W6, gm[5], bt[5], A,  32, 256); }

    // 4. bilinear resize to (256,200,200)
    resize_kernel<<<(256 * 200 * 200 + 255) / 256, 256>>>(A, (float*)d_out);
}